// round 13
// baseline (speedup 1.0000x reference)
#include <cuda_runtime.h>
#include <cuda_bf16.h>
#include <cstdint>

#define NUM_HEADS 12
#define HEAD_DIM  64
#define SEQ       2048
#define BATCH     2
#define EMB       768
#define SEG       256
#define KDIM      768

// Scratch — EXACT R4/R8/R9 set (proven to pass the allocation guard)
__device__ float g_q[BATCH*NUM_HEADS*SEQ*HEAD_DIM];
__device__ float g_k[BATCH*NUM_HEADS*SEQ*HEAD_DIM];
__device__ float g_v[BATCH*NUM_HEADS*SEQ*HEAD_DIM];
__device__ float g_ctx[BATCH*SEQ*EMB];

// ===========================================================================
// Warp-level MMA helpers (compute_100-safe: sm_80-era PTX)
// ===========================================================================
__device__ __forceinline__ uint32_t smem_u32(const void* p) {
  uint32_t a;
  asm("{ .reg .u64 t; cvta.to.shared.u64 t, %1; cvt.u32.u64 %0, t; }" : "=r"(a) : "l"(p));
  return a;
}
__device__ __forceinline__ void ldsm4(uint32_t* r, uint32_t addr) {
  asm volatile("ldmatrix.sync.aligned.m8n8.x4.shared.b16 {%0,%1,%2,%3}, [%4];"
               : "=r"(r[0]), "=r"(r[1]), "=r"(r[2]), "=r"(r[3]) : "r"(addr));
}
__device__ __forceinline__ void ldsm4t(uint32_t* r, uint32_t addr) {
  asm volatile("ldmatrix.sync.aligned.m8n8.x4.trans.shared.b16 {%0,%1,%2,%3}, [%4];"
               : "=r"(r[0]), "=r"(r[1]), "=r"(r[2]), "=r"(r[3]) : "r"(addr));
}
__device__ __forceinline__ void mma_bf16(float* d, const uint32_t* a,
                                         uint32_t b0, uint32_t b1) {
  asm volatile(
      "mma.sync.aligned.m16n8k16.row.col.f32.bf16.bf16.f32 "
      "{%0,%1,%2,%3}, {%4,%5,%6,%7}, {%8,%9}, {%0,%1,%2,%3};"
      : "+f"(d[0]), "+f"(d[1]), "+f"(d[2]), "+f"(d[3])
      : "r"(a[0]), "r"(a[1]), "r"(a[2]), "r"(a[3]), "r"(b0), "r"(b1));
}

#define SWZ(off) ((off) ^ (((off) >> 3) & 0x70))

__device__ __forceinline__ uint32_t pack2(float a, float b) {
  __nv_bfloat162 p = __halves2bfloat162(__float2bfloat16(a), __float2bfloat16(b));
  return *reinterpret_cast<uint32_t*>(&p);
}

// ===========================================================================
// GEMM v5: CTA tile 128(M) x 256(N), 256 threads, warp grid 2x4, warp tile
// 64x64 (6 MMA per ldsm vs R8's 4 => ~1.66x less L1 traffic per FLOP).
// A (activations) register-prefetched as in R8; B (weights, L2-hot) staged
// inline. Split-bf16 3-pass, fp32 register accumulators.
// mode 0: QKV (blockIdx.z selects q/k/v, scatter to (B,H,S,D))
// mode 1: out projection (row-major to dout)
// ===========================================================================
#define GK      64
#define NCHUNK  (KDIM / GK)            // 12
#define SA_HI   0                      // 128 rows * 128B = 16384
#define SA_LO   16384
#define SB_HI   32768                  // 256 rows * 128B = 32768
#define SB_LO   65536
#define GEMM_SMEM 98304

__global__ __launch_bounds__(256) void gemm_hmma_kernel(
    const float* __restrict__ A0,
    const float* __restrict__ W0, const float* __restrict__ b0,
    const float* __restrict__ W1, const float* __restrict__ b1,
    const float* __restrict__ W2, const float* __restrict__ b2,
    float* __restrict__ dout, int mode) {
  extern __shared__ char sm[];
  const uint32_t sbase = smem_u32(sm);
  const int tid  = threadIdx.x;
  const int wid  = tid >> 5;
  const int lane = tid & 31;
  const int m0 = blockIdx.y * 128;
  const int n0 = blockIdx.x * 256;
  const int z  = blockIdx.z;

  const float* A    = (mode == 1) ? g_ctx : A0;
  const float* W    = (z == 0) ? W0 : (z == 1) ? W1 : W2;
  const float* bias = (z == 0) ? b0 : (z == 1) ? b1 : b2;
  float* outp = (mode == 1) ? dout : ((z == 0) ? g_q : (z == 1) ? g_k : g_v);

  // A staging (R8 scheme): thread covers row r, K half cb; prefetched
  const int r  = tid >> 1;
  const int cb = (tid & 1) * 32;
  const float* Ap = A + (size_t)(m0 + r) * KDIM + cb;
  // B staging: one full 64-col row per thread, inline LDG
  const float* Wp = W + (size_t)(n0 + tid) * KDIM;

  // warp tile: 2(M) x 4(N) grid of 64x64
  const int mw = (wid >> 2) * 64;      // 0,64
  const int nw = (wid & 3) * 64;       // 0,64,128,192
  const int lrow = lane & 15;
  const int lkb  = (lane >> 4) * 16;

  // acc[mi*8 + nb*2 + ni][4] : mi 0..3, nb 0..3, ni 0..1
  float acc[32][4];
#pragma unroll
  for (int i = 0; i < 32; i++)
#pragma unroll
    for (int j = 0; j < 4; j++) acc[i][j] = 0.f;

  // ---- prologue: prefetch A chunk 0 ----
  float4 pa[8];
#pragma unroll
  for (int u = 0; u < 8; u++) pa[u] = *(const float4*)(Ap + u * 4);

  for (int c = 0; c < NCHUNK; c++) {
    // ---- stage B (inline, 16 independent LDGs for MLP) ----
#pragma unroll
    for (int u = 0; u < 16; u++) {
      float4 wv = *(const float4*)(Wp + c * GK + u * 4);
      const uint32_t sw = SWZ((uint32_t)(tid * 128 + u * 8));
      float whx = __bfloat162float(__float2bfloat16(wv.x));
      float why = __bfloat162float(__float2bfloat16(wv.y));
      float whz = __bfloat162float(__float2bfloat16(wv.z));
      float whw = __bfloat162float(__float2bfloat16(wv.w));
      *(uint2*)(sm + SB_HI + sw) = make_uint2(pack2(whx, why), pack2(whz, whw));
      *(uint2*)(sm + SB_LO + sw) =
          make_uint2(pack2(wv.x - whx, wv.y - why), pack2(wv.z - whz, wv.w - whw));
    }
    // ---- stage A from prefetched registers ----
#pragma unroll
    for (int u = 0; u < 8; u++) {
      const float4 av = pa[u];
      const uint32_t sw = SWZ((uint32_t)(r * 128 + (cb + u * 4) * 2));
      float ahx = __bfloat162float(__float2bfloat16(av.x));
      float ahy = __bfloat162float(__float2bfloat16(av.y));
      float ahz = __bfloat162float(__float2bfloat16(av.z));
      float ahw = __bfloat162float(__float2bfloat16(av.w));
      *(uint2*)(sm + SA_HI + sw) = make_uint2(pack2(ahx, ahy), pack2(ahz, ahw));
      *(uint2*)(sm + SA_LO + sw) =
          make_uint2(pack2(av.x - ahx, av.y - ahy), pack2(av.z - ahz, av.w - ahw));
    }
    __syncthreads();

    // ---- prefetch A chunk c+1 (retires behind MMA phase) ----
    if (c + 1 < NCHUNK) {
#pragma unroll
      for (int u = 0; u < 8; u++)
        pa[u] = *(const float4*)(Ap + (c + 1) * GK + u * 4);
    }

    // ---- compute: 4 K16 steps; per ks: 16 ldsm, 96 mma ----
#pragma unroll
    for (int ks = 0; ks < 4; ks++) {
      const uint32_t koff = (uint32_t)(ks * 32 + lkb);
      uint32_t ah[4][4], al[4][4];
#pragma unroll
      for (int mi = 0; mi < 4; mi++) {
        const uint32_t off = (uint32_t)((mw + mi * 16 + lrow) * 128) + koff;
        ldsm4(ah[mi], sbase + SA_HI + SWZ(off));
        ldsm4(al[mi], sbase + SA_LO + SWZ(off));
      }
#pragma unroll
      for (int nb = 0; nb < 4; nb++) {
        uint32_t bh[4], bl[4];
        const uint32_t off = (uint32_t)((nw + nb * 16 + lrow) * 128) + koff;
        ldsm4(bh, sbase + SB_HI + SWZ(off));
        ldsm4(bl, sbase + SB_LO + SWZ(off));
#pragma unroll
        for (int ni = 0; ni < 2; ni++) {
          const uint32_t b0 = bh[ni], b1 = bh[2 + ni];
          const uint32_t c0 = bl[ni], c1 = bl[2 + ni];
#pragma unroll
          for (int mi = 0; mi < 4; mi++) {
            float* a = acc[mi * 8 + nb * 2 + ni];
            mma_bf16(a, ah[mi], b0, b1);  // hi*hi
            mma_bf16(a, ah[mi], c0, c1);  // hi*lo
            mma_bf16(a, al[mi], b0, b1);  // lo*hi
          }
        }
      }
    }
    __syncthreads();
  }

  // ---- epilogue: bias add + store ----
  const int er = lane >> 2;        // 0..7
  const int ec = (lane & 3) * 2;   // 0,2,4,6
#pragma unroll
  for (int mi = 0; mi < 4; mi++) {
#pragma unroll
    for (int rr = 0; rr < 2; rr++) {
      const int m = m0 + mw + mi * 16 + rr * 8 + er;
      if (mode == 1) {
        float* orow = outp + (size_t)m * EMB;
#pragma unroll
        for (int nb = 0; nb < 4; nb++)
#pragma unroll
          for (int ni = 0; ni < 2; ni++) {
            const int n = n0 + nw + nb * 16 + ni * 8 + ec;
            float2 v;
            v.x = acc[mi * 8 + nb * 2 + ni][rr * 2 + 0] + bias[n];
            v.y = acc[mi * 8 + nb * 2 + ni][rr * 2 + 1] + bias[n + 1];
            *(float2*)(orow + n) = v;
          }
      } else {
        const int b = m >> 11;
        const int s = m & 2047;
#pragma unroll
        for (int nb = 0; nb < 4; nb++)
#pragma unroll
          for (int ni = 0; ni < 2; ni++) {
            const int n = n0 + nw + nb * 16 + ni * 8 + ec;
            const int h = n >> 6;
            const int d = n & 63;
            float2 v;
            v.x = acc[mi * 8 + nb * 2 + ni][rr * 2 + 0] + bias[n];
            v.y = acc[mi * 8 + nb * 2 + ni][rr * 2 + 1] + bias[n + 1];
            *(float2*)(outp + (((size_t)b * NUM_HEADS + h) * SEQ + s) * HEAD_DIM + d) = v;
          }
      }
    }
  }
}

// ===========================================================================
// HMMA attention (R12-proven, untouched). Block-diagonal over 256-token segs.
// ===========================================================================
#define AT_QHI  0
#define AT_QLO  8192
#define AT_KHI  16384
#define AT_KLO  49152
#define AT_PHI  81920
#define AT_PLO  114688
#define AT_VHI  147456
#define AT_VLO  180224
#define AT_REDM 212992
#define AT_REDS 214016
#define AT_RINV 215040
#define ATTN_SMEM 215296

__global__ __launch_bounds__(256) void attn_kernel() {
  extern __shared__ char sm[];
  const uint32_t sbase = smem_u32(sm);
  float* REDM = (float*)(sm + AT_REDM);
  float* REDS = (float*)(sm + AT_REDS);
  float* RINV = (float*)(sm + AT_RINV);

  const int tid  = threadIdx.x;
  const int wid  = tid >> 5;
  const int lane = tid & 31;
  int bx = blockIdx.x;
  const int qt  = bx & 3;   bx >>= 2;
  const int seg = bx & 7;   bx >>= 3;
  const int hh  = bx % NUM_HEADS;
  const int bb  = bx / NUM_HEADS;

  const size_t head_off = (((size_t)bb*NUM_HEADS + hh)*SEQ + seg*SEG) * HEAD_DIM;
  const float* qbase = g_q + head_off + (size_t)qt*64*HEAD_DIM;
  const float* kbase = g_k + head_off;
  const float* vbase = g_v + head_off;

  {
    const int r  = tid >> 2;
    const int c0 = (tid & 3) * 16;
#pragma unroll
    for (int u = 0; u < 4; u++) {
      float4 v = *(const float4*)(qbase + r * 64 + c0 + u * 4);
      v.x *= 0.125f; v.y *= 0.125f; v.z *= 0.125f; v.w *= 0.125f;
      const uint32_t sw = SWZ((uint32_t)(r * 128 + (c0 + u * 4) * 2));
      float hx = __bfloat162float(__float2bfloat16(v.x));
      float hy = __bfloat162float(__float2bfloat16(v.y));
      float hz = __bfloat162float(__float2bfloat16(v.z));
      float hw = __bfloat162float(__float2bfloat16(v.w));
      *(uint2*)(sm + AT_QHI + sw) = make_uint2(pack2(hx, hy), pack2(hz, hw));
      *(uint2*)(sm + AT_QLO + sw) =
          make_uint2(pack2(v.x - hx, v.y - hy), pack2(v.z - hz, v.w - hw));
    }
  }
  {
    const int j = tid;
#pragma unroll
    for (int u = 0; u < 16; u++) {
      const uint32_t sw = SWZ((uint32_t)(j * 128 + u * 8));
      float4 v = *(const float4*)(kbase + j * 64 + u * 4);
      float hx = __bfloat162float(__float2bfloat16(v.x));
      float hy = __bfloat162float(__float2bfloat16(v.y));
      float hz = __bfloat162float(__float2bfloat16(v.z));
      float hw = __bfloat162float(__float2bfloat16(v.w));
      *(uint2*)(sm + AT_KHI + sw) = make_uint2(pack2(hx, hy), pack2(hz, hw));
      *(uint2*)(sm + AT_KLO + sw) =
          make_uint2(pack2(v.x - hx, v.y - hy), pack2(v.z - hz, v.w - hw));

      float4 w = *(const float4*)(vbase + j * 64 + u * 4);
      float gx = __bfloat162float(__float2bfloat16(w.x));
      float gy = __bfloat162float(__float2bfloat16(w.y));
      float gz = __bfloat162float(__float2bfloat16(w.z));
      float gw = __bfloat162float(__float2bfloat16(w.w));
      *(uint2*)(sm + AT_VHI + sw) = make_uint2(pack2(gx, gy), pack2(gz, gw));
      *(uint2*)(sm + AT_VLO + sw) =
          make_uint2(pack2(w.x - gx, w.y - gy), pack2(w.z - gz, w.w - gw));
    }
  }
  __syncthreads();

  const int mw = (wid >> 2) * 32;
  const int nw = (wid & 3) * 64;
  const int lrow = lane & 15;
  const int lkb  = (lane >> 4) * 16;

  float acc[16][4];
#pragma unroll
  for (int i = 0; i < 16; i++)
#pragma unroll
    for (int j = 0; j < 4; j++) acc[i][j] = 0.f;

#pragma unroll
  for (int ks = 0; ks < 4; ks++) {
    const uint32_t koff = (uint32_t)(ks * 32 + lkb);
    uint32_t ah[2][4], al[2][4];
#pragma unroll
    for (int mi = 0; mi < 2; mi++) {
      const uint32_t off = (uint32_t)((mw + mi * 16 + lrow) * 128) + koff;
      ldsm4(ah[mi], sbase + AT_QHI + SWZ(off));
      ldsm4(al[mi], sbase + AT_QLO + SWZ(off));
    }
    uint32_t bh[4][4], bl[4][4];
#pragma unroll
    for (int nb = 0; nb < 4; nb++) {
      const uint32_t off = (uint32_t)((nw + nb * 16 + lrow) * 128) + koff;
      ldsm4(bh[nb], sbase + AT_KHI + SWZ(off));
      ldsm4(bl[nb], sbase + AT_KLO + SWZ(off));
    }
#pragma unroll
    for (int ni = 0; ni < 8; ni++) {
      const int nb = ni >> 1, sel = ni & 1;
      const uint32_t bh0 = bh[nb][sel], bh1 = bh[nb][2 + sel];
      const uint32_t bl0 = bl[nb][sel], bl1 = bl[nb][2 + sel];
#pragma unroll
      for (int mi = 0; mi < 2; mi++) {
        mma_bf16(acc[mi * 8 + ni], ah[mi], bh0, bh1);
        mma_bf16(acc[mi * 8 + ni], ah[mi], bl0, bl1);
        mma_bf16(acc[mi * 8 + ni], al[mi], bh0, bh1);
      }
    }
  }

  const int er = lane >> 2;
  const int ec = (lane & 3) * 2;
  const int wcol = wid & 3;

#pragma unroll
  for (int mi = 0; mi < 2; mi++)
#pragma unroll
    for (int rr = 0; rr < 2; rr++) {
      float m = -1e30f;
#pragma unroll
      for (int ni = 0; ni < 8; ni++) {
        m = fmaxf(m, acc[mi * 8 + ni][rr * 2 + 0]);
        m = fmaxf(m, acc[mi * 8 + ni][rr * 2 + 1]);
      }
      m = fmaxf(m, __shfl_xor_sync(0xffffffffu, m, 1));
      m = fmaxf(m, __shfl_xor_sync(0xffffffffu, m, 2));
      if ((lane & 3) == 0)
        REDM[wcol * 64 + mw + mi * 16 + rr * 8 + er] = m;
    }
  __syncthreads();

  const uint32_t ppan = (uint32_t)wcol * 8192;
#pragma unroll
  for (int mi = 0; mi < 2; mi++)
#pragma unroll
    for (int rr = 0; rr < 2; rr++) {
      const int m = mw + mi * 16 + rr * 8 + er;
      float fm = fmaxf(fmaxf(REDM[m], REDM[64 + m]),
                       fmaxf(REDM[128 + m], REDM[192 + m]));
      float s = 0.f;
#pragma unroll
      for (int ni = 0; ni < 8; ni++) {
        float e0 = __expf(acc[mi * 8 + ni][rr * 2 + 0] - fm);
        float e1 = __expf(acc[mi * 8 + ni][rr * 2 + 1] - fm);
        s += e0 + e1;
        float h0 = __bfloat162float(__float2bfloat16(e0));
        float h1 = __bfloat162float(__float2bfloat16(e1));
        const uint32_t sw = SWZ((uint32_t)(m * 128 + (ni * 8 + ec) * 2));
        *(uint32_t*)(sm + AT_PHI + ppan + sw) = pack2(h0, h1);
        *(uint32_t*)(sm + AT_PLO + ppan + sw) = pack2(e0 - h0, e1 - h1);
      }
      s += __shfl_xor_sync(0xffffffffu, s, 1);
      s += __shfl_xor_sync(0xffffffffu, s, 2);
      if ((lane & 3) == 0) REDS[wcol * 64 + m] = s;
    }
  __syncthreads();

  if (wcol == 0 && (lane & 3) == 0) {
#pragma unroll
    for (int mi = 0; mi < 2; mi++)
#pragma unroll
      for (int rr = 0; rr < 2; rr++) {
        const int m = mw + mi * 16 + rr * 8 + er;
        RINV[m] = 1.0f / (REDS[m] + REDS[64 + m] + REDS[128 + m] + REDS[192 + m]);
      }
  }
  __syncthreads();

  const int nw2 = (wid & 3) * 16;
  const int trow = (lane & 7) + ((lane >> 4) << 3);
  const int tcol = ((lane >> 3) & 1) << 3;
  float accv[4][4];
#pragma unroll
  for (int i = 0; i < 4; i++)
#pragma unroll
    for (int j = 0; j < 4; j++) accv[i][j] = 0.f;

#pragma unroll
  for (int pp = 0; pp < 4; pp++) {
    const uint32_t pb = (uint32_t)pp * 8192;
#pragma unroll
    for (int ks = 0; ks < 4; ks++) {
      const uint32_t koff = (uint32_t)(ks * 32 + lkb);
      uint32_t ph[2][4], pl[2][4];
#pragma unroll
      for (int mi = 0; mi < 2; mi++) {
        const uint32_t off = (uint32_t)((mw + mi * 16 + lrow) * 128) + koff;
        ldsm4(ph[mi], sbase + AT_PHI + pb + SWZ(off));
        ldsm4(pl[mi], sbase + AT_PLO + pb + SWZ(off));
      }
      uint32_t vh[4], vl[4];
      {
        const int jg = pp * 64 + ks * 16 + trow;
        const uint32_t off = SWZ((uint32_t)(jg * 128 + (nw2 + tcol) * 2));
        ldsm4t(vh, sbase + AT_VHI + off);
        ldsm4t(vl, sbase + AT_VLO + off);
      }
#pragma unroll
      for (int ni = 0; ni < 2; ni++) {
        const uint32_t b0 = vh[ni], b1 = vh[2 + ni];
        const uint32_t c0 = vl[ni], c1 = vl[2 + ni];
#pragma unroll
        for (int mi = 0; mi < 2; mi++) {
          mma_bf16(accv[mi * 2 + ni], ph[mi], b0, b1);
          mma_bf16(accv[mi * 2 + ni], ph[mi], c0, c1);
          mma_bf16(accv[mi * 2 + ni], pl[mi], b0, b1);
        }
      }
    }
  }

  float* ctxbase = g_ctx + ((size_t)bb*SEQ + seg*SEG + qt*64)*EMB + hh*64;
#pragma unroll
  for (int mi = 0; mi < 2; mi++) {
#pragma unroll
    for (int rr = 0; rr < 2; rr++) {
      const int m = mw + mi * 16 + rr * 8 + er;
      const float iv = RINV[m];
#pragma unroll
      for (int ni = 0; ni < 2; ni++) {
        const int d = nw2 + ni * 8 + ec;
        float2 v;
        v.x = accv[mi * 2 + ni][rr * 2 + 0] * iv;
        v.y = accv[mi * 2 + ni][rr * 2 + 1] * iv;
        *(float2*)(ctxbase + (size_t)m * EMB + d) = v;
      }
    }
  }
}

// ===========================================================================
extern "C" void kernel_launch(void* const* d_in, const int* in_sizes, int n_in,
                              void* d_out, int out_size) {
  const float* x  = (const float*)d_in[0];
  const float* Wq = (const float*)d_in[1];
  const float* bq = (const float*)d_in[2];
  const float* Wk = (const float*)d_in[3];
  const float* bk = (const float*)d_in[4];
  const float* Wv = (const float*)d_in[5];
  const float* bv = (const float*)d_in[6];
  const float* Wo = (const float*)d_in[7];
  const float* bo = (const float*)d_in[8];
  float* out = (float*)d_out;

  cudaFuncSetAttribute(gemm_hmma_kernel,
                       cudaFuncAttributeMaxDynamicSharedMemorySize, GEMM_SMEM);
  cudaFuncSetAttribute(attn_kernel,
                       cudaFuncAttributeMaxDynamicSharedMemorySize, ATTN_SMEM);

  dim3 gqkv(3, 32, 3);
  gemm_hmma_kernel<<<gqkv, 256, GEMM_SMEM>>>(x, Wq, bq, Wk, bk, Wv, bv,
                                             nullptr, 0);

  attn_kernel<<<768, 256, ATTN_SMEM>>>();

  dim3 gout(3, 32, 1);
  gemm_hmma_kernel<<<gout, 256, GEMM_SMEM>>>(nullptr, Wo, bo, Wo, bo, Wo, bo,
                                             out, 1);
}

// round 14
// speedup vs baseline: 1.1598x; 1.1598x over previous
#include <cuda_runtime.h>
#include <cuda_bf16.h>
#include <cstdint>

#define NUM_HEADS 12
#define HEAD_DIM  64
#define SEQ       2048
#define BATCH     2
#define EMB       768
#define SEG       256
#define KDIM      768

// Scratch — EXACT R4/R8/R9 set (proven to pass the allocation guard)
__device__ float g_q[BATCH*NUM_HEADS*SEQ*HEAD_DIM];
__device__ float g_k[BATCH*NUM_HEADS*SEQ*HEAD_DIM];
__device__ float g_v[BATCH*NUM_HEADS*SEQ*HEAD_DIM];
__device__ float g_ctx[BATCH*SEQ*EMB];

// ===========================================================================
// Warp-level MMA helpers (compute_100-safe: sm_80-era PTX)
// ===========================================================================
__device__ __forceinline__ uint32_t smem_u32(const void* p) {
  uint32_t a;
  asm("{ .reg .u64 t; cvta.to.shared.u64 t, %1; cvt.u32.u64 %0, t; }" : "=r"(a) : "l"(p));
  return a;
}
__device__ __forceinline__ void ldsm4(uint32_t* r, uint32_t addr) {
  asm volatile("ldmatrix.sync.aligned.m8n8.x4.shared.b16 {%0,%1,%2,%3}, [%4];"
               : "=r"(r[0]), "=r"(r[1]), "=r"(r[2]), "=r"(r[3]) : "r"(addr));
}
__device__ __forceinline__ void ldsm4t(uint32_t* r, uint32_t addr) {
  asm volatile("ldmatrix.sync.aligned.m8n8.x4.trans.shared.b16 {%0,%1,%2,%3}, [%4];"
               : "=r"(r[0]), "=r"(r[1]), "=r"(r[2]), "=r"(r[3]) : "r"(addr));
}
__device__ __forceinline__ void mma_bf16(float* d, const uint32_t* a,
                                         uint32_t b0, uint32_t b1) {
  asm volatile(
      "mma.sync.aligned.m16n8k16.row.col.f32.bf16.bf16.f32 "
      "{%0,%1,%2,%3}, {%4,%5,%6,%7}, {%8,%9}, {%0,%1,%2,%3};"
      : "+f"(d[0]), "+f"(d[1]), "+f"(d[2]), "+f"(d[3])
      : "r"(a[0]), "r"(a[1]), "r"(a[2]), "r"(a[3]), "r"(b0), "r"(b1));
}

#define SWZ(off) ((off) ^ (((off) >> 3) & 0x70))

__device__ __forceinline__ uint32_t pack2(float a, float b) {
  __nv_bfloat162 p = __halves2bfloat162(__float2bfloat16(a), __float2bfloat16(b));
  return *reinterpret_cast<uint32_t*>(&p);
}

// ===========================================================================
// GEMM (R8-proven local optimum, FROZEN): C = A*W^T + bias, split-bf16
// 3-pass, single 64KB smem buffer, register prefetch of chunk c+1.
// ===========================================================================
#define GK      64
#define NCHUNK  (KDIM / GK)            // 12
#define OFF_AHI 0
#define OFF_ALO 16384
#define OFF_BHI 32768
#define OFF_BLO 49152
#define GEMM_SMEM 65536

__global__ __launch_bounds__(256) void gemm_hmma_kernel(
    const float* __restrict__ A0,
    const float* __restrict__ W0, const float* __restrict__ b0,
    const float* __restrict__ W1, const float* __restrict__ b1,
    const float* __restrict__ W2, const float* __restrict__ b2,
    float* __restrict__ dout, int mode) {
  extern __shared__ char sm[];
  const uint32_t sbase = smem_u32(sm);
  const int tid  = threadIdx.x;
  const int wid  = tid >> 5;
  const int lane = tid & 31;
  const int m0 = blockIdx.y * 128;
  const int n0 = blockIdx.x * 128;
  const int z  = blockIdx.z;

  const float* A    = (mode == 1) ? g_ctx : A0;
  const float* W    = (z == 0) ? W0 : (z == 1) ? W1 : W2;
  const float* bias = (z == 0) ? b0 : (z == 1) ? b1 : b2;
  float* outp = (mode == 1) ? dout : ((z == 0) ? g_q : (z == 1) ? g_k : g_v);

  const int r  = tid >> 1;
  const int cb = (tid & 1) * 32;
  const float* Ap = A + (size_t)(m0 + r) * KDIM + cb;
  const float* Wp = W + (size_t)(n0 + r) * KDIM + cb;

  const int mw = (wid >> 1) * 32;
  const int nw = (wid & 1) * 64;
  const int lrow = lane & 15;
  const int lkb  = (lane >> 4) * 16;

  float acc[16][4];
#pragma unroll
  for (int i = 0; i < 16; i++)
#pragma unroll
    for (int j = 0; j < 4; j++) acc[i][j] = 0.f;

  float4 pa[8], pw[8];
#pragma unroll
  for (int u = 0; u < 8; u++) {
    pa[u] = *(const float4*)(Ap + u * 4);
    pw[u] = *(const float4*)(Wp + u * 4);
  }

  for (int c = 0; c < NCHUNK; c++) {
#pragma unroll
    for (int u = 0; u < 8; u++) {
      const float4 av = pa[u];
      const float4 wv = pw[u];
      const uint32_t sw = SWZ((uint32_t)(r * 128 + (cb + u * 4) * 2));

      float ahx = __bfloat162float(__float2bfloat16(av.x));
      float ahy = __bfloat162float(__float2bfloat16(av.y));
      float ahz = __bfloat162float(__float2bfloat16(av.z));
      float ahw = __bfloat162float(__float2bfloat16(av.w));
      *(uint2*)(sm + OFF_AHI + sw) = make_uint2(pack2(ahx, ahy), pack2(ahz, ahw));
      *(uint2*)(sm + OFF_ALO + sw) =
          make_uint2(pack2(av.x - ahx, av.y - ahy), pack2(av.z - ahz, av.w - ahw));

      float whx = __bfloat162float(__float2bfloat16(wv.x));
      float why = __bfloat162float(__float2bfloat16(wv.y));
      float whz = __bfloat162float(__float2bfloat16(wv.z));
      float whw = __bfloat162float(__float2bfloat16(wv.w));
      *(uint2*)(sm + OFF_BHI + sw) = make_uint2(pack2(whx, why), pack2(whz, whw));
      *(uint2*)(sm + OFF_BLO + sw) =
          make_uint2(pack2(wv.x - whx, wv.y - why), pack2(wv.z - whz, wv.w - whw));
    }
    __syncthreads();

    if (c + 1 < NCHUNK) {
#pragma unroll
      for (int u = 0; u < 8; u++) {
        pa[u] = *(const float4*)(Ap + (c + 1) * GK + u * 4);
        pw[u] = *(const float4*)(Wp + (c + 1) * GK + u * 4);
      }
    }

#pragma unroll
    for (int ks = 0; ks < 4; ks++) {
      const uint32_t koff = (uint32_t)(ks * 32 + lkb);
      uint32_t ah[2][4], al[2][4];
#pragma unroll
      for (int mi = 0; mi < 2; mi++) {
        const uint32_t off = (uint32_t)((mw + mi * 16 + lrow) * 128) + koff;
        ldsm4(ah[mi], sbase + OFF_AHI + SWZ(off));
        ldsm4(al[mi], sbase + OFF_ALO + SWZ(off));
      }
      uint32_t bh[4][4], bl[4][4];
#pragma unroll
      for (int nb = 0; nb < 4; nb++) {
        const uint32_t off = (uint32_t)((nw + nb * 16 + lrow) * 128) + koff;
        ldsm4(bh[nb], sbase + OFF_BHI + SWZ(off));
        ldsm4(bl[nb], sbase + OFF_BLO + SWZ(off));
      }
#pragma unroll
      for (int ni = 0; ni < 8; ni++) {
        const int nb = ni >> 1, sel = ni & 1;
        const uint32_t bh0 = bh[nb][sel], bh1 = bh[nb][2 + sel];
        const uint32_t bl0 = bl[nb][sel], bl1 = bl[nb][2 + sel];
#pragma unroll
        for (int mi = 0; mi < 2; mi++) {
          mma_bf16(acc[mi * 8 + ni], ah[mi], bh0, bh1);
          mma_bf16(acc[mi * 8 + ni], ah[mi], bl0, bl1);
          mma_bf16(acc[mi * 8 + ni], al[mi], bh0, bh1);
        }
      }
    }
    __syncthreads();
  }

  const int er = lane >> 2;
  const int ec = (lane & 3) * 2;
#pragma unroll
  for (int mi = 0; mi < 2; mi++) {
#pragma unroll
    for (int rr = 0; rr < 2; rr++) {
      const int m = m0 + mw + mi * 16 + rr * 8 + er;
      if (mode == 1) {
        float* orow = outp + (size_t)m * EMB;
#pragma unroll
        for (int ni = 0; ni < 8; ni++) {
          const int n = n0 + nw + ni * 8 + ec;
          float2 v;
          v.x = acc[mi * 8 + ni][rr * 2 + 0] + bias[n];
          v.y = acc[mi * 8 + ni][rr * 2 + 1] + bias[n + 1];
          *(float2*)(orow + n) = v;
        }
      } else {
        const int b = m >> 11;
        const int s = m & 2047;
#pragma unroll
        for (int ni = 0; ni < 8; ni++) {
          const int n = n0 + nw + ni * 8 + ec;
          const int h = n >> 6;
          const int d = n & 63;
          float2 v;
          v.x = acc[mi * 8 + ni][rr * 2 + 0] + bias[n];
          v.y = acc[mi * 8 + ni][rr * 2 + 1] + bias[n + 1];
          *(float2*)(outp + (((size_t)b * NUM_HEADS + h) * SEQ + s) * HEAD_DIM + d) = v;
        }
      }
    }
  }
}

// ===========================================================================
// HMMA attention v2: flash-style over two 128-token j-tiles.
// smem 84KB -> 2 CTAs/SM (cross-CTA overlap of staging and MMA).
// Running max M, running sum L, rescale factor f per owned row.
// One CTA per (b, h, seg, 64-row qtile): grid 768, 256 threads (8 warps).
// ===========================================================================
#define AQ_HI   0                      // Q 64x128B hi
#define AQ_LO   8192
#define AB_HI   16384                  // K/V tile 128x128B hi
#define AB_LO   32768
#define AP_HI   49152                  // P 2 panels x 64x128B hi
#define AP_LO   65536
#define AREDM   81920                  // 4*64 floats
#define AREDS   82944                  // 4*64 floats
#define ATTN_SMEM 83968

__global__ __launch_bounds__(256, 2) void attn_kernel() {
  extern __shared__ char sm[];
  const uint32_t sbase = smem_u32(sm);
  float* REDM = (float*)(sm + AREDM);
  float* REDS = (float*)(sm + AREDS);

  const int tid  = threadIdx.x;
  const int wid  = tid >> 5;
  const int lane = tid & 31;
  int bx = blockIdx.x;
  const int qt  = bx & 3;   bx >>= 2;
  const int seg = bx & 7;   bx >>= 3;
  const int hh  = bx % NUM_HEADS;
  const int bb  = bx / NUM_HEADS;

  const size_t head_off = (((size_t)bb*NUM_HEADS + hh)*SEQ + seg*SEG) * HEAD_DIM;
  const float* qbase = g_q + head_off + (size_t)qt*64*HEAD_DIM;
  const float* kbase = g_k + head_off;
  const float* vbase = g_v + head_off;

  // warp/lane coords
  const int mw   = (wid >> 2) * 32;    // 0,32
  const int wcol = wid & 3;            // 32-col stripe within 128-j tile
  const int lrow = lane & 15;
  const int lkb  = (lane >> 4) * 16;
  const int er   = lane >> 2;
  const int ec   = (lane & 3) * 2;
  const int nw2  = wcol * 16;          // d stripe for PV
  const int trow = (lane & 7) + ((lane >> 4) << 3);
  const int tcol = ((lane >> 3) & 1) << 3;

  // staging coords (128-row tiles)
  const int sr  = tid >> 1;            // 0..127
  const int scb = (tid & 1) * 32;

  // ---- stage Q (scaled 0.125) hi/lo ----
  {
    const int r  = tid >> 2;
    const int c0 = (tid & 3) * 16;
#pragma unroll
    for (int u = 0; u < 4; u++) {
      float4 v = *(const float4*)(qbase + r * 64 + c0 + u * 4);
      v.x *= 0.125f; v.y *= 0.125f; v.z *= 0.125f; v.w *= 0.125f;
      const uint32_t sw = SWZ((uint32_t)(r * 128 + (c0 + u * 4) * 2));
      float hx = __bfloat162float(__float2bfloat16(v.x));
      float hy = __bfloat162float(__float2bfloat16(v.y));
      float hz = __bfloat162float(__float2bfloat16(v.z));
      float hw = __bfloat162float(__float2bfloat16(v.w));
      *(uint2*)(sm + AQ_HI + sw) = make_uint2(pack2(hx, hy), pack2(hz, hw));
      *(uint2*)(sm + AQ_LO + sw) =
          make_uint2(pack2(v.x - hx, v.y - hy), pack2(v.z - hz, v.w - hw));
    }
  }

  float accv[4][4];
#pragma unroll
  for (int i = 0; i < 4; i++)
#pragma unroll
    for (int j = 0; j < 4; j++) accv[i][j] = 0.f;
  float Mrow[2][2] = {{-1e30f, -1e30f}, {-1e30f, -1e30f}};
  float Lrow[2][2] = {{0.f, 0.f}, {0.f, 0.f}};

  for (int h = 0; h < 2; h++) {
    // ---- stage K tile h (ABUF free: fresh or post-PV sync) ----
    {
      const float* src = kbase + (size_t)(h * 128 + sr) * 64 + scb;
#pragma unroll
      for (int u = 0; u < 8; u++) {
        float4 v = *(const float4*)(src + u * 4);
        const uint32_t sw = SWZ((uint32_t)(sr * 128 + (scb + u * 4) * 2));
        float hx = __bfloat162float(__float2bfloat16(v.x));
        float hy = __bfloat162float(__float2bfloat16(v.y));
        float hz = __bfloat162float(__float2bfloat16(v.z));
        float hw = __bfloat162float(__float2bfloat16(v.w));
        *(uint2*)(sm + AB_HI + sw) = make_uint2(pack2(hx, hy), pack2(hz, hw));
        *(uint2*)(sm + AB_LO + sw) =
            make_uint2(pack2(v.x - hx, v.y - hy), pack2(v.z - hz, v.w - hw));
      }
    }
    __syncthreads();                       // (1) K staged

    // ---- S-half: 64 x 128, warp stripe 32 cols ----
    float sacc[8][4];
#pragma unroll
    for (int i = 0; i < 8; i++)
#pragma unroll
      for (int j = 0; j < 4; j++) sacc[i][j] = 0.f;

#pragma unroll
    for (int ks = 0; ks < 4; ks++) {
      const uint32_t koff = (uint32_t)(ks * 32 + lkb);
      uint32_t ah[2][4], al[2][4];
#pragma unroll
      for (int mi = 0; mi < 2; mi++) {
        const uint32_t off = (uint32_t)((mw + mi * 16 + lrow) * 128) + koff;
        ldsm4(ah[mi], sbase + AQ_HI + SWZ(off));
        ldsm4(al[mi], sbase + AQ_LO + SWZ(off));
      }
      uint32_t bh[2][4], bl[2][4];
#pragma unroll
      for (int nb = 0; nb < 2; nb++) {
        const uint32_t off = (uint32_t)((wcol * 32 + nb * 16 + lrow) * 128) + koff;
        ldsm4(bh[nb], sbase + AB_HI + SWZ(off));
        ldsm4(bl[nb], sbase + AB_LO + SWZ(off));
      }
#pragma unroll
      for (int ni = 0; ni < 4; ni++) {
        const int nb = ni >> 1, sel = ni & 1;
        const uint32_t b0 = bh[nb][sel], b1 = bh[nb][2 + sel];
        const uint32_t c0 = bl[nb][sel], c1 = bl[nb][2 + sel];
#pragma unroll
        for (int mi = 0; mi < 2; mi++) {
          mma_bf16(sacc[mi * 4 + ni], ah[mi], b0, b1);
          mma_bf16(sacc[mi * 4 + ni], ah[mi], c0, c1);
          mma_bf16(sacc[mi * 4 + ni], al[mi], b0, b1);
        }
      }
    }

    // ---- partial row max -> REDM ----
#pragma unroll
    for (int mi = 0; mi < 2; mi++)
#pragma unroll
      for (int rr = 0; rr < 2; rr++) {
        float mx = -1e30f;
#pragma unroll
        for (int ni = 0; ni < 4; ni++) {
          mx = fmaxf(mx, sacc[mi * 4 + ni][rr * 2 + 0]);
          mx = fmaxf(mx, sacc[mi * 4 + ni][rr * 2 + 1]);
        }
        mx = fmaxf(mx, __shfl_xor_sync(0xffffffffu, mx, 1));
        mx = fmaxf(mx, __shfl_xor_sync(0xffffffffu, mx, 2));
        if ((lane & 3) == 0)
          REDM[wcol * 64 + mw + mi * 16 + rr * 8 + er] = mx;
      }
    __syncthreads();                       // (2) REDM ready; all S ldsm done

    // ---- exp + P write + REDS partial; then stage V into ABUF ----
    float fr[2][2];
#pragma unroll
    for (int mi = 0; mi < 2; mi++)
#pragma unroll
      for (int rr = 0; rr < 2; rr++) {
        const int m = mw + mi * 16 + rr * 8 + er;
        const float fm = fmaxf(fmaxf(REDM[m], REDM[64 + m]),
                               fmaxf(REDM[128 + m], REDM[192 + m]));
        const float Mn = fmaxf(Mrow[mi][rr], fm);
        fr[mi][rr] = __expf(Mrow[mi][rr] - Mn);
        Mrow[mi][rr] = Mn;
        float s = 0.f;
#pragma unroll
        for (int ni = 0; ni < 4; ni++) {
          float e0 = __expf(sacc[mi * 4 + ni][rr * 2 + 0] - Mn);
          float e1 = __expf(sacc[mi * 4 + ni][rr * 2 + 1] - Mn);
          s += e0 + e1;
          const int colh = wcol * 32 + ni * 8 + ec;
          const int p = colh >> 6, cp = colh & 63;
          float h0 = __bfloat162float(__float2bfloat16(e0));
          float h1 = __bfloat162float(__float2bfloat16(e1));
          const uint32_t sw = SWZ((uint32_t)(m * 128 + cp * 2));
          *(uint32_t*)(sm + AP_HI + p * 8192 + sw) = pack2(h0, h1);
          *(uint32_t*)(sm + AP_LO + p * 8192 + sw) = pack2(e0 - h0, e1 - h1);
        }
        s += __shfl_xor_sync(0xffffffffu, s, 1);
        s += __shfl_xor_sync(0xffffffffu, s, 2);
        if ((lane & 3) == 0) REDS[wcol * 64 + m] = s;
      }
    // stage V tile h (safe: sync (2) ordered all K reads)
    {
      const float* src = vbase + (size_t)(h * 128 + sr) * 64 + scb;
#pragma unroll
      for (int u = 0; u < 8; u++) {
        float4 v = *(const float4*)(src + u * 4);
        const uint32_t sw = SWZ((uint32_t)(sr * 128 + (scb + u * 4) * 2));
        float hx = __bfloat162float(__float2bfloat16(v.x));
        float hy = __bfloat162float(__float2bfloat16(v.y));
        float hz = __bfloat162float(__float2bfloat16(v.z));
        float hw = __bfloat162float(__float2bfloat16(v.w));
        *(uint2*)(sm + AB_HI + sw) = make_uint2(pack2(hx, hy), pack2(hz, hw));
        *(uint2*)(sm + AB_LO + sw) =
            make_uint2(pack2(v.x - hx, v.y - hy), pack2(v.z - hz, v.w - hw));
      }
    }
    __syncthreads();                       // (3) V, P, REDS ready

    // ---- finalize L, rescale accv ----
#pragma unroll
    for (int mi = 0; mi < 2; mi++)
#pragma unroll
      for (int rr = 0; rr < 2; rr++) {
        const int m = mw + mi * 16 + rr * 8 + er;
        const float sh = REDS[m] + REDS[64 + m] + REDS[128 + m] + REDS[192 + m];
        const float f = fr[mi][rr];
        Lrow[mi][rr] = Lrow[mi][rr] * f + sh;
#pragma unroll
        for (int ni = 0; ni < 2; ni++) {
          accv[mi * 2 + ni][rr * 2 + 0] *= f;
          accv[mi * 2 + ni][rr * 2 + 1] *= f;
        }
      }

    // ---- PV: accv += P_h(64x128) @ V_h(128x64) ----
#pragma unroll
    for (int pp = 0; pp < 2; pp++) {
      const uint32_t pb = (uint32_t)pp * 8192;
#pragma unroll
      for (int ks = 0; ks < 4; ks++) {
        const uint32_t koff = (uint32_t)(ks * 32 + lkb);
        uint32_t ph[2][4], pl[2][4];
#pragma unroll
        for (int mi = 0; mi < 2; mi++) {
          const uint32_t off = (uint32_t)((mw + mi * 16 + lrow) * 128) + koff;
          ldsm4(ph[mi], sbase + AP_HI + pb + SWZ(off));
          ldsm4(pl[mi], sbase + AP_LO + pb + SWZ(off));
        }
        uint32_t vh[4], vl[4];
        {
          const int jg = pp * 64 + ks * 16 + trow;
          const uint32_t off = SWZ((uint32_t)(jg * 128 + (nw2 + tcol) * 2));
          ldsm4t(vh, sbase + AB_HI + off);
          ldsm4t(vl, sbase + AB_LO + off);
        }
#pragma unroll
        for (int ni = 0; ni < 2; ni++) {
          const uint32_t b0 = vh[ni], b1 = vh[2 + ni];
          const uint32_t c0 = vl[ni], c1 = vl[2 + ni];
#pragma unroll
          for (int mi = 0; mi < 2; mi++) {
            mma_bf16(accv[mi * 2 + ni], ph[mi], b0, b1);
            mma_bf16(accv[mi * 2 + ni], ph[mi], c0, c1);
            mma_bf16(accv[mi * 2 + ni], pl[mi], b0, b1);
          }
        }
      }
    }
    __syncthreads();                       // (4) buffers reusable next half
  }

  // ---- epilogue: normalize by 1/L, scatter to (B,S,E) ----
  float* ctxbase = g_ctx + ((size_t)bb*SEQ + seg*SEG + qt*64)*EMB + hh*64;
#pragma unroll
  for (int mi = 0; mi < 2; mi++) {
#pragma unroll
    for (int rr = 0; rr < 2; rr++) {
      const int m = mw + mi * 16 + rr * 8 + er;
      const float iv = 1.0f / Lrow[mi][rr];
#pragma unroll
      for (int ni = 0; ni < 2; ni++) {
        const int d = nw2 + ni * 8 + ec;
        float2 v;
        v.x = accv[mi * 2 + ni][rr * 2 + 0] * iv;
        v.y = accv[mi * 2 + ni][rr * 2 + 1] * iv;
        *(float2*)(ctxbase + (size_t)m * EMB + d) = v;
      }
    }
  }
}

// ===========================================================================
extern "C" void kernel_launch(void* const* d_in, const int* in_sizes, int n_in,
                              void* d_out, int out_size) {
  const float* x  = (const float*)d_in[0];
  const float* Wq = (const float*)d_in[1];
  const float* bq = (const float*)d_in[2];
  const float* Wk = (const float*)d_in[3];
  const float* bk = (const float*)d_in[4];
  const float* Wv = (const float*)d_in[5];
  const float* bv = (const float*)d_in[6];
  const float* Wo = (const float*)d_in[7];
  const float* bo = (const float*)d_in[8];
  float* out = (float*)d_out;

  cudaFuncSetAttribute(gemm_hmma_kernel,
                       cudaFuncAttributeMaxDynamicSharedMemorySize, GEMM_SMEM);
  cudaFuncSetAttribute(attn_kernel,
                       cudaFuncAttributeMaxDynamicSharedMemorySize, ATTN_SMEM);

  dim3 gqkv(6, 32, 3);
  gemm_hmma_kernel<<<gqkv, 256, GEMM_SMEM>>>(x, Wq, bq, Wk, bk, Wv, bv,
                                             nullptr, 0);

  attn_kernel<<<768, 256, ATTN_SMEM>>>();

  dim3 gout(6, 32, 1);
  gemm_hmma_kernel<<<gout, 256, GEMM_SMEM>>>(nullptr, Wo, bo, Wo, bo, Wo, bo,
                                             out, 1);
}

// round 16
// speedup vs baseline: 1.3265x; 1.1438x over previous
#include <cuda_runtime.h>
#include <cuda_bf16.h>
#include <cstdint>

#define NUM_HEADS 12
#define HEAD_DIM  64
#define SEQ       2048
#define BATCH     2
#define EMB       768
#define SEG       256
#define KDIM      768
#define MTOT      (BATCH*SEQ)
#define QKV_N     (BATCH*NUM_HEADS*SEQ*HEAD_DIM)   // 3145728

// Globals: 8 bf16 arrays x 6.29 MB = 50.33 MB == R4's proven-passing footprint.
__device__ __nv_bfloat16 g_qhi[QKV_N];
__device__ __nv_bfloat16 g_qlo[QKV_N];
__device__ __nv_bfloat16 g_khi[QKV_N];
__device__ __nv_bfloat16 g_klo[QKV_N];
__device__ __nv_bfloat16 g_vhi[QKV_N];
__device__ __nv_bfloat16 g_vlo[QKV_N];
__device__ __nv_bfloat16 g_chi[MTOT*EMB];   // x-splits, then ctx-splits
__device__ __nv_bfloat16 g_clo[MTOT*EMB];

// ===========================================================================
// Helpers (compute_100-safe: sm_80-era PTX)
// ===========================================================================
__device__ __forceinline__ uint32_t smem_u32(const void* p) {
  uint32_t a;
  asm("{ .reg .u64 t; cvta.to.shared.u64 t, %1; cvt.u32.u64 %0, t; }" : "=r"(a) : "l"(p));
  return a;
}
__device__ __forceinline__ void ldsm4(uint32_t* r, uint32_t addr) {
  asm volatile("ldmatrix.sync.aligned.m8n8.x4.shared.b16 {%0,%1,%2,%3}, [%4];"
               : "=r"(r[0]), "=r"(r[1]), "=r"(r[2]), "=r"(r[3]) : "r"(addr));
}
__device__ __forceinline__ void ldsm4t(uint32_t* r, uint32_t addr) {
  asm volatile("ldmatrix.sync.aligned.m8n8.x4.trans.shared.b16 {%0,%1,%2,%3}, [%4];"
               : "=r"(r[0]), "=r"(r[1]), "=r"(r[2]), "=r"(r[3]) : "r"(addr));
}
__device__ __forceinline__ void mma_bf16(float* d, const uint32_t* a,
                                         uint32_t b0, uint32_t b1) {
  asm volatile(
      "mma.sync.aligned.m16n8k16.row.col.f32.bf16.bf16.f32 "
      "{%0,%1,%2,%3}, {%4,%5,%6,%7}, {%8,%9}, {%0,%1,%2,%3};"
      : "+f"(d[0]), "+f"(d[1]), "+f"(d[2]), "+f"(d[3])
      : "r"(a[0]), "r"(a[1]), "r"(a[2]), "r"(a[3]), "r"(b0), "r"(b1));
}

#define SWZ(off) ((off) ^ (((off) >> 3) & 0x70))

__device__ __forceinline__ uint32_t pack2(float a, float b) {
  __nv_bfloat162 p = __halves2bfloat162(__float2bfloat16(a), __float2bfloat16(b));
  return *reinterpret_cast<uint32_t*>(&p);
}

// ===========================================================================
// x pre-split: fp32 -> bf16 hi/lo into g_chi/g_clo
// ===========================================================================
__global__ __launch_bounds__(256) void convx_kernel(const float4* __restrict__ src) {
  const int i = blockIdx.x * 256 + threadIdx.x;
  float4 v = src[i];
  float hx = __bfloat162float(__float2bfloat16(v.x));
  float hy = __bfloat162float(__float2bfloat16(v.y));
  float hz = __bfloat162float(__float2bfloat16(v.z));
  float hw = __bfloat162float(__float2bfloat16(v.w));
  ((uint2*)g_chi)[i] = make_uint2(pack2(hx, hy), pack2(hz, hw));
  ((uint2*)g_clo)[i] = make_uint2(pack2(v.x - hx, v.y - hy), pack2(v.z - hz, v.w - hw));
}

// ===========================================================================
// GEMM (R8 skeleton): A staged by PURE COPY from g_chi/g_clo; W (fp32)
// converted in-kernel as in R8. Register prefetch of chunk c+1.
// mode 0: QKV — epilogue splits (acc+bias)*(z==0?0.125:1) into q/k/v hi/lo
// mode 1: out projection — epilogue writes fp32 row-major to dout
// ===========================================================================
#define GK      64
#define NCHUNK  (KDIM / GK)            // 12
#define OFF_AHI 0
#define OFF_ALO 16384
#define OFF_BHI 32768
#define OFF_BLO 49152
#define GEMM_SMEM 65536

__global__ __launch_bounds__(256) void gemm_hmma_kernel(
    const float* __restrict__ W0, const float* __restrict__ b0,
    const float* __restrict__ W1, const float* __restrict__ b1,
    const float* __restrict__ W2, const float* __restrict__ b2,
    float* __restrict__ dout, int mode) {
  extern __shared__ char sm[];
  const uint32_t sbase = smem_u32(sm);
  const int tid  = threadIdx.x;
  const int wid  = tid >> 5;
  const int lane = tid & 31;
  const int m0 = blockIdx.y * 128;
  const int n0 = blockIdx.x * 128;
  const int z  = blockIdx.z;

  const float* W    = (z == 0) ? W0 : (z == 1) ? W1 : W2;
  const float* bias = (z == 0) ? b0 : (z == 1) ? b1 : b2;

  const int r  = tid >> 1;
  const int cb = (tid & 1) * 32;
  const __nv_bfloat16* Aph = g_chi + (size_t)(m0 + r) * KDIM + cb;
  const __nv_bfloat16* Apl = g_clo + (size_t)(m0 + r) * KDIM + cb;
  const float* Wp = W + (size_t)(n0 + r) * KDIM + cb;

  const int mw = (wid >> 1) * 32;
  const int nw = (wid & 1) * 64;
  const int lrow = lane & 15;
  const int lkb  = (lane >> 4) * 16;

  uint32_t dsw[4];
#pragma unroll
  for (int j = 0; j < 4; j++)
    dsw[j] = SWZ((uint32_t)(r * 128 + cb * 2 + j * 16));

  float acc[16][4];
#pragma unroll
  for (int i = 0; i < 16; i++)
#pragma unroll
    for (int j = 0; j < 4; j++) acc[i][j] = 0.f;

  // ---- prologue: prefetch chunk 0 ----
  uint4 pah[4], pal[4];
  float4 pw[8];
#pragma unroll
  for (int j = 0; j < 4; j++) {
    pah[j] = *(const uint4*)(Aph + j * 8);
    pal[j] = *(const uint4*)(Apl + j * 8);
  }
#pragma unroll
  for (int u = 0; u < 8; u++) pw[u] = *(const float4*)(Wp + u * 4);

  for (int c = 0; c < NCHUNK; c++) {
    // ---- stage A: pure STS.128 ----
#pragma unroll
    for (int j = 0; j < 4; j++) {
      *(uint4*)(sm + OFF_AHI + dsw[j]) = pah[j];
      *(uint4*)(sm + OFF_ALO + dsw[j]) = pal[j];
    }
    // ---- stage W: fp32 -> hi/lo (R8 path) ----
#pragma unroll
    for (int u = 0; u < 8; u++) {
      const float4 wv = pw[u];
      const uint32_t sw = SWZ((uint32_t)(r * 128 + (cb + u * 4) * 2));
      float whx = __bfloat162float(__float2bfloat16(wv.x));
      float why = __bfloat162float(__float2bfloat16(wv.y));
      float whz = __bfloat162float(__float2bfloat16(wv.z));
      float whw = __bfloat162float(__float2bfloat16(wv.w));
      *(uint2*)(sm + OFF_BHI + sw) = make_uint2(pack2(whx, why), pack2(whz, whw));
      *(uint2*)(sm + OFF_BLO + sw) =
          make_uint2(pack2(wv.x - whx, wv.y - why), pack2(wv.z - whz, wv.w - whw));
    }
    __syncthreads();

    // ---- prefetch chunk c+1 (retires behind MMA phase) ----
    if (c + 1 < NCHUNK) {
      const int ko = (c + 1) * GK;
#pragma unroll
      for (int j = 0; j < 4; j++) {
        pah[j] = *(const uint4*)(Aph + ko + j * 8);
        pal[j] = *(const uint4*)(Apl + ko + j * 8);
      }
#pragma unroll
      for (int u = 0; u < 8; u++) pw[u] = *(const float4*)(Wp + ko + u * 4);
    }

    // ---- compute chunk c (R8-verbatim) ----
#pragma unroll
    for (int ks = 0; ks < 4; ks++) {
      const uint32_t koff = (uint32_t)(ks * 32 + lkb);
      uint32_t ah[2][4], al[2][4];
#pragma unroll
      for (int mi = 0; mi < 2; mi++) {
        const uint32_t off = (uint32_t)((mw + mi * 16 + lrow) * 128) + koff;
        ldsm4(ah[mi], sbase + OFF_AHI + SWZ(off));
        ldsm4(al[mi], sbase + OFF_ALO + SWZ(off));
      }
      uint32_t bh[4][4], bl[4][4];
#pragma unroll
      for (int nb = 0; nb < 4; nb++) {
        const uint32_t off = (uint32_t)((nw + nb * 16 + lrow) * 128) + koff;
        ldsm4(bh[nb], sbase + OFF_BHI + SWZ(off));
        ldsm4(bl[nb], sbase + OFF_BLO + SWZ(off));
      }
#pragma unroll
      for (int ni = 0; ni < 8; ni++) {
        const int nb = ni >> 1, sel = ni & 1;
        const uint32_t bh0 = bh[nb][sel], bh1 = bh[nb][2 + sel];
        const uint32_t bl0 = bl[nb][sel], bl1 = bl[nb][2 + sel];
#pragma unroll
        for (int mi = 0; mi < 2; mi++) {
          mma_bf16(acc[mi * 8 + ni], ah[mi], bh0, bh1);
          mma_bf16(acc[mi * 8 + ni], ah[mi], bl0, bl1);
          mma_bf16(acc[mi * 8 + ni], al[mi], bh0, bh1);
        }
      }
    }
    __syncthreads();
  }

  // ---- epilogue ----
  const int er = lane >> 2;
  const int ec = (lane & 3) * 2;
#pragma unroll
  for (int mi = 0; mi < 2; mi++) {
#pragma unroll
    for (int rr = 0; rr < 2; rr++) {
      const int m = m0 + mw + mi * 16 + rr * 8 + er;
      if (mode == 1) {
        float* orow = dout + (size_t)m * EMB;
#pragma unroll
        for (int ni = 0; ni < 8; ni++) {
          const int n = n0 + nw + ni * 8 + ec;
          float2 v;
          v.x = acc[mi * 8 + ni][rr * 2 + 0] + bias[n];
          v.y = acc[mi * 8 + ni][rr * 2 + 1] + bias[n + 1];
          *(float2*)(orow + n) = v;
        }
      } else {
        __nv_bfloat16* ohi = (z == 0) ? g_qhi : (z == 1) ? g_khi : g_vhi;
        __nv_bfloat16* olo = (z == 0) ? g_qlo : (z == 1) ? g_klo : g_vlo;
        const float qs = (z == 0) ? 0.125f : 1.0f;   // fold Q scale, exact
        const int b = m >> 11;
        const int s = m & 2047;
#pragma unroll
        for (int ni = 0; ni < 8; ni++) {
          const int n = n0 + nw + ni * 8 + ec;
          const int h = n >> 6;
          const int d = n & 63;
          float fx = (acc[mi * 8 + ni][rr * 2 + 0] + bias[n]) * qs;
          float fy = (acc[mi * 8 + ni][rr * 2 + 1] + bias[n + 1]) * qs;
          float hx = __bfloat162float(__float2bfloat16(fx));
          float hy = __bfloat162float(__float2bfloat16(fy));
          const size_t o = (((size_t)b * NUM_HEADS + h) * SEQ + s) * HEAD_DIM + d;
          *(uint32_t*)(ohi + o) = pack2(hx, hy);
          *(uint32_t*)(olo + o) = pack2(fx - hx, fy - hy);
        }
      }
    }
  }
}

// ===========================================================================
// HMMA flash attention (R14 structure; staging = PURE COPIES of pre-split
// q/k/v; epilogue emits ctx hi/lo into g_chi/g_clo for the out-projection).
// ===========================================================================
#define AQ_HI   0
#define AQ_LO   8192
#define AB_HI   16384
#define AB_LO   32768
#define AP_HI   49152
#define AP_LO   65536
#define AREDM   81920
#define AREDS   82944
#define ATTN_SMEM 83968

__global__ __launch_bounds__(256, 2) void attn_kernel() {
  extern __shared__ char sm[];
  const uint32_t sbase = smem_u32(sm);
  float* REDM = (float*)(sm + AREDM);
  float* REDS = (float*)(sm + AREDS);

  const int tid  = threadIdx.x;
  const int wid  = tid >> 5;
  const int lane = tid & 31;
  int bx = blockIdx.x;
  const int qt  = bx & 3;   bx >>= 2;
  const int seg = bx & 7;   bx >>= 3;
  const int hh  = bx % NUM_HEADS;
  const int bb  = bx / NUM_HEADS;

  const size_t head_off = (((size_t)bb*NUM_HEADS + hh)*SEQ + seg*SEG) * HEAD_DIM;
  const size_t qoff = head_off + (size_t)qt*64*HEAD_DIM;

  const int mw   = (wid >> 2) * 32;
  const int wcol = wid & 3;
  const int lrow = lane & 15;
  const int lkb  = (lane >> 4) * 16;
  const int er   = lane >> 2;
  const int ec   = (lane & 3) * 2;
  const int nw2  = wcol * 16;
  const int trow = (lane & 7) + ((lane >> 4) << 3);
  const int tcol = ((lane >> 3) & 1) << 3;

  const int sr  = tid >> 1;
  const int scb = (tid & 1) * 32;

  // ---- stage Q: pure copies (pre-scaled at projection time) ----
  {
    const int r   = tid >> 2;
    const int c0e = (tid & 3) * 16;     // element offset
#pragma unroll
    for (int j = 0; j < 2; j++) {
      const uint32_t sw = SWZ((uint32_t)(r * 128 + c0e * 2 + j * 16));
      *(uint4*)(sm + AQ_HI + sw) = *(const uint4*)(g_qhi + qoff + r * 64 + c0e + j * 8);
      *(uint4*)(sm + AQ_LO + sw) = *(const uint4*)(g_qlo + qoff + r * 64 + c0e + j * 8);
    }
  }

  float accv[4][4];
#pragma unroll
  for (int i = 0; i < 4; i++)
#pragma unroll
    for (int j = 0; j < 4; j++) accv[i][j] = 0.f;
  float Mrow[2][2] = {{-1e30f, -1e30f}, {-1e30f, -1e30f}};
  float Lrow[2][2] = {{0.f, 0.f}, {0.f, 0.f}};

  for (int h = 0; h < 2; h++) {
    // ---- stage K tile h: pure copies ----
    {
      const size_t so = head_off + (size_t)(h * 128 + sr) * 64 + scb;
#pragma unroll
      for (int j = 0; j < 4; j++) {
        const uint32_t sw = SWZ((uint32_t)(sr * 128 + scb * 2 + j * 16));
        *(uint4*)(sm + AB_HI + sw) = *(const uint4*)(g_khi + so + j * 8);
        *(uint4*)(sm + AB_LO + sw) = *(const uint4*)(g_klo + so + j * 8);
      }
    }
    __syncthreads();                       // (1) K staged

    float sacc[8][4];
#pragma unroll
    for (int i = 0; i < 8; i++)
#pragma unroll
      for (int j = 0; j < 4; j++) sacc[i][j] = 0.f;

#pragma unroll
    for (int ks = 0; ks < 4; ks++) {
      const uint32_t koff = (uint32_t)(ks * 32 + lkb);
      uint32_t ah[2][4], al[2][4];
#pragma unroll
      for (int mi = 0; mi < 2; mi++) {
        const uint32_t off = (uint32_t)((mw + mi * 16 + lrow) * 128) + koff;
        ldsm4(ah[mi], sbase + AQ_HI + SWZ(off));
        ldsm4(al[mi], sbase + AQ_LO + SWZ(off));
      }
      uint32_t bh[2][4], bl[2][4];
#pragma unroll
      for (int nb = 0; nb < 2; nb++) {
        const uint32_t off = (uint32_t)((wcol * 32 + nb * 16 + lrow) * 128) + koff;
        ldsm4(bh[nb], sbase + AB_HI + SWZ(off));
        ldsm4(bl[nb], sbase + AB_LO + SWZ(off));
      }
#pragma unroll
      for (int ni = 0; ni < 4; ni++) {
        const int nb = ni >> 1, sel = ni & 1;
        const uint32_t b0 = bh[nb][sel], b1 = bh[nb][2 + sel];
        const uint32_t c0 = bl[nb][sel], c1 = bl[nb][2 + sel];
#pragma unroll
        for (int mi = 0; mi < 2; mi++) {
          mma_bf16(sacc[mi * 4 + ni], ah[mi], b0, b1);
          mma_bf16(sacc[mi * 4 + ni], ah[mi], c0, c1);
          mma_bf16(sacc[mi * 4 + ni], al[mi], b0, b1);
        }
      }
    }

#pragma unroll
    for (int mi = 0; mi < 2; mi++)
#pragma unroll
      for (int rr = 0; rr < 2; rr++) {
        float mx = -1e30f;
#pragma unroll
        for (int ni = 0; ni < 4; ni++) {
          mx = fmaxf(mx, sacc[mi * 4 + ni][rr * 2 + 0]);
          mx = fmaxf(mx, sacc[mi * 4 + ni][rr * 2 + 1]);
        }
        mx = fmaxf(mx, __shfl_xor_sync(0xffffffffu, mx, 1));
        mx = fmaxf(mx, __shfl_xor_sync(0xffffffffu, mx, 2));
        if ((lane & 3) == 0)
          REDM[wcol * 64 + mw + mi * 16 + rr * 8 + er] = mx;
      }
    __syncthreads();                       // (2) REDM ready; K reads done

    float fr[2][2];
#pragma unroll
    for (int mi = 0; mi < 2; mi++)
#pragma unroll
      for (int rr = 0; rr < 2; rr++) {
        const int m = mw + mi * 16 + rr * 8 + er;
        const float fm = fmaxf(fmaxf(REDM[m], REDM[64 + m]),
                               fmaxf(REDM[128 + m], REDM[192 + m]));
        const float Mn = fmaxf(Mrow[mi][rr], fm);
        fr[mi][rr] = __expf(Mrow[mi][rr] - Mn);
        Mrow[mi][rr] = Mn;
        float s = 0.f;
#pragma unroll
        for (int ni = 0; ni < 4; ni++) {
          float e0 = __expf(sacc[mi * 4 + ni][rr * 2 + 0] - Mn);
          float e1 = __expf(sacc[mi * 4 + ni][rr * 2 + 1] - Mn);
          s += e0 + e1;
          const int colh = wcol * 32 + ni * 8 + ec;
          const int p = colh >> 6, cp = colh & 63;
          float h0 = __bfloat162float(__float2bfloat16(e0));
          float h1 = __bfloat162float(__float2bfloat16(e1));
          const uint32_t sw = SWZ((uint32_t)(m * 128 + cp * 2));
          *(uint32_t*)(sm + AP_HI + p * 8192 + sw) = pack2(h0, h1);
          *(uint32_t*)(sm + AP_LO + p * 8192 + sw) = pack2(e0 - h0, e1 - h1);
        }
        s += __shfl_xor_sync(0xffffffffu, s, 1);
        s += __shfl_xor_sync(0xffffffffu, s, 2);
        if ((lane & 3) == 0) REDS[wcol * 64 + m] = s;
      }
    // ---- stage V tile h: pure copies (safe after sync (2)) ----
    {
      const size_t so = head_off + (size_t)(h * 128 + sr) * 64 + scb;
#pragma unroll
      for (int j = 0; j < 4; j++) {
        const uint32_t sw = SWZ((uint32_t)(sr * 128 + scb * 2 + j * 16));
        *(uint4*)(sm + AB_HI + sw) = *(const uint4*)(g_vhi + so + j * 8);
        *(uint4*)(sm + AB_LO + sw) = *(const uint4*)(g_vlo + so + j * 8);
      }
    }
    __syncthreads();                       // (3) V, P, REDS ready

#pragma unroll
    for (int mi = 0; mi < 2; mi++)
#pragma unroll
      for (int rr = 0; rr < 2; rr++) {
        const int m = mw + mi * 16 + rr * 8 + er;
        const float sh = REDS[m] + REDS[64 + m] + REDS[128 + m] + REDS[192 + m];
        const float f = fr[mi][rr];
        Lrow[mi][rr] = Lrow[mi][rr] * f + sh;
#pragma unroll
        for (int ni = 0; ni < 2; ni++) {
          accv[mi * 2 + ni][rr * 2 + 0] *= f;
          accv[mi * 2 + ni][rr * 2 + 1] *= f;
        }
      }

#pragma unroll
    for (int pp = 0; pp < 2; pp++) {
      const uint32_t pb = (uint32_t)pp * 8192;
#pragma unroll
      for (int ks = 0; ks < 4; ks++) {
        const uint32_t koff = (uint32_t)(ks * 32 + lkb);
        uint32_t ph[2][4], pl[2][4];
#pragma unroll
        for (int mi = 0; mi < 2; mi++) {
          const uint32_t off = (uint32_t)((mw + mi * 16 + lrow) * 128) + koff;
          ldsm4(ph[mi], sbase + AP_HI + pb + SWZ(off));
          ldsm4(pl[mi], sbase + AP_LO + pb + SWZ(off));
        }
        uint32_t vh[4], vl[4];
        {
          const int jg = pp * 64 + ks * 16 + trow;
          const uint32_t off = SWZ((uint32_t)(jg * 128 + (nw2 + tcol) * 2));
          ldsm4t(vh, sbase + AB_HI + off);
          ldsm4t(vl, sbase + AB_LO + off);
        }
#pragma unroll
        for (int ni = 0; ni < 2; ni++) {
          const uint32_t b0 = vh[ni], b1 = vh[2 + ni];
          const uint32_t c0 = vl[ni], c1 = vl[2 + ni];
#pragma unroll
          for (int mi = 0; mi < 2; mi++) {
            mma_bf16(accv[mi * 2 + ni], ph[mi], b0, b1);
            mma_bf16(accv[mi * 2 + ni], ph[mi], c0, c1);
            mma_bf16(accv[mi * 2 + ni], pl[mi], b0, b1);
          }
        }
      }
    }
    __syncthreads();                       // (4) buffers reusable next half
  }

  // ---- epilogue: normalize by 1/L, emit ctx as bf16 hi/lo splits ----
  const size_t cb0 = ((size_t)bb*SEQ + seg*SEG + qt*64)*EMB + hh*64;
#pragma unroll
  for (int mi = 0; mi < 2; mi++) {
#pragma unroll
    for (int rr = 0; rr < 2; rr++) {
      const int m = mw + mi * 16 + rr * 8 + er;
      const float iv = 1.0f / Lrow[mi][rr];
#pragma unroll
      for (int ni = 0; ni < 2; ni++) {
        const int d = nw2 + ni * 8 + ec;
        float fx = accv[mi * 2 + ni][rr * 2 + 0] * iv;
        float fy = accv[mi * 2 + ni][rr * 2 + 1] * iv;
        float hx = __bfloat162float(__float2bfloat16(fx));
        float hy = __bfloat162float(__float2bfloat16(fy));
        const size_t o = cb0 + (size_t)m * EMB + d;
        *(uint32_t*)(g_chi + o) = pack2(hx, hy);
        *(uint32_t*)(g_clo + o) = pack2(fx - hx, fy - hy);
      }
    }
  }
}

// ===========================================================================
extern "C" void kernel_launch(void* const* d_in, const int* in_sizes, int n_in,
                              void* d_out, int out_size) {
  const float* x  = (const float*)d_in[0];
  const float* Wq = (const float*)d_in[1];
  const float* bq = (const float*)d_in[2];
  const float* Wk = (const float*)d_in[3];
  const float* bk = (const float*)d_in[4];
  const float* Wv = (const float*)d_in[5];
  const float* bv = (const float*)d_in[6];
  const float* Wo = (const float*)d_in[7];
  const float* bo = (const float*)d_in[8];
  float* out = (float*)d_out;

  cudaFuncSetAttribute(gemm_hmma_kernel,
                       cudaFuncAttributeMaxDynamicSharedMemorySize, GEMM_SMEM);
  cudaFuncSetAttribute(attn_kernel,
                       cudaFuncAttributeMaxDynamicSharedMemorySize, ATTN_SMEM);

  // pre-split x into g_chi/g_clo
  convx_kernel<<<MTOT * KDIM / 4 / 256, 256>>>((const float4*)x);

  dim3 gqkv(6, 32, 3);
  gemm_hmma_kernel<<<gqkv, 256, GEMM_SMEM>>>(Wq, bq, Wk, bk, Wv, bv,
                                             nullptr, 0);

  attn_kernel<<<768, 256, ATTN_SMEM>>>();

  dim3 gout(6, 32, 1);
  gemm_hmma_kernel<<<gout, 256, GEMM_SMEM>>>(Wo, bo, Wo, bo, Wo, bo,
                                             out, 1);
}

// round 17
// speedup vs baseline: 1.4453x; 1.0895x over previous
#include <cuda_runtime.h>
#include <cuda_bf16.h>
#include <cstdint>

#define NUM_HEADS 12
#define HEAD_DIM  64
#define SEQ       2048
#define BATCH     2
#define EMB       768
#define SEG       256
#define KDIM      768
#define MTOT      (BATCH*SEQ)
#define QKV_N     (BATCH*NUM_HEADS*SEQ*HEAD_DIM)   // 3145728
#define WELEM     (EMB*KDIM)                        // 589824

// Globals: 50.33 MB — the proven-passing footprint. d_out doubles as scratch
// for x-splits (dead by the time the final output is written).
__device__ __nv_bfloat16 g_qhi[QKV_N];
__device__ __nv_bfloat16 g_qlo[QKV_N];
__device__ __nv_bfloat16 g_khi[QKV_N];   // k-splits; then Wo-splits (hi at [0,WELEM))
__device__ __nv_bfloat16 g_klo[QKV_N];
__device__ __nv_bfloat16 g_vhi[QKV_N];
__device__ __nv_bfloat16 g_vlo[QKV_N];
__device__ __nv_bfloat16 g_chi[MTOT*EMB]; // Wq/Wk/Wv-splits (3*WELEM), then ctx-splits
__device__ __nv_bfloat16 g_clo[MTOT*EMB];

// ===========================================================================
// Helpers (compute_100-safe: sm_80-era PTX)
// ===========================================================================
__device__ __forceinline__ uint32_t smem_u32(const void* p) {
  uint32_t a;
  asm("{ .reg .u64 t; cvta.to.shared.u64 t, %1; cvt.u32.u64 %0, t; }" : "=r"(a) : "l"(p));
  return a;
}
__device__ __forceinline__ void ldsm4(uint32_t* r, uint32_t addr) {
  asm volatile("ldmatrix.sync.aligned.m8n8.x4.shared.b16 {%0,%1,%2,%3}, [%4];"
               : "=r"(r[0]), "=r"(r[1]), "=r"(r[2]), "=r"(r[3]) : "r"(addr));
}
__device__ __forceinline__ void ldsm4t(uint32_t* r, uint32_t addr) {
  asm volatile("ldmatrix.sync.aligned.m8n8.x4.trans.shared.b16 {%0,%1,%2,%3}, [%4];"
               : "=r"(r[0]), "=r"(r[1]), "=r"(r[2]), "=r"(r[3]) : "r"(addr));
}
__device__ __forceinline__ void mma_bf16(float* d, const uint32_t* a,
                                         uint32_t b0, uint32_t b1) {
  asm volatile(
      "mma.sync.aligned.m16n8k16.row.col.f32.bf16.bf16.f32 "
      "{%0,%1,%2,%3}, {%4,%5,%6,%7}, {%8,%9}, {%0,%1,%2,%3};"
      : "+f"(d[0]), "+f"(d[1]), "+f"(d[2]), "+f"(d[3])
      : "r"(a[0]), "r"(a[1]), "r"(a[2]), "r"(a[3]), "r"(b0), "r"(b1));
}

#define SWZ(off) ((off) ^ (((off) >> 3) & 0x70))

__device__ __forceinline__ uint32_t pack2(float a, float b) {
  __nv_bfloat162 p = __halves2bfloat162(__float2bfloat16(a), __float2bfloat16(b));
  return *reinterpret_cast<uint32_t*>(&p);
}

// ===========================================================================
// Conversion kernels
// ===========================================================================
// x -> [hi | lo] bf16 halves of d_out
__global__ __launch_bounds__(256) void convx_kernel(const float4* __restrict__ src,
                                                    __nv_bfloat16* __restrict__ xsp) {
  const int i = blockIdx.x * 256 + threadIdx.x;
  float4 v = src[i];
  float hx = __bfloat162float(__float2bfloat16(v.x));
  float hy = __bfloat162float(__float2bfloat16(v.y));
  float hz = __bfloat162float(__float2bfloat16(v.z));
  float hw = __bfloat162float(__float2bfloat16(v.w));
  ((uint2*)xsp)[i] = make_uint2(pack2(hx, hy), pack2(hz, hw));
  ((uint2*)(xsp + (size_t)MTOT * KDIM))[i] =
      make_uint2(pack2(v.x - hx, v.y - hy), pack2(v.z - hz, v.w - hw));
}

// Wq/Wk/Wv -> g_chi/g_clo at z*WELEM
__global__ __launch_bounds__(256) void convw3_kernel(const float4* __restrict__ w0,
                                                     const float4* __restrict__ w1,
                                                     const float4* __restrict__ w2) {
  const int z = blockIdx.y;
  const float4* src = (z == 0) ? w0 : (z == 1) ? w1 : w2;
  const int i = blockIdx.x * 256 + threadIdx.x;
  float4 v = src[i];
  float hx = __bfloat162float(__float2bfloat16(v.x));
  float hy = __bfloat162float(__float2bfloat16(v.y));
  float hz = __bfloat162float(__float2bfloat16(v.z));
  float hw = __bfloat162float(__float2bfloat16(v.w));
  ((uint2*)(g_chi + (size_t)z * WELEM))[i] = make_uint2(pack2(hx, hy), pack2(hz, hw));
  ((uint2*)(g_clo + (size_t)z * WELEM))[i] =
      make_uint2(pack2(v.x - hx, v.y - hy), pack2(v.z - hz, v.w - hw));
}

// Wo -> g_khi/g_klo (k-splits dead after attention)
__global__ __launch_bounds__(256) void convwo_kernel(const float4* __restrict__ src) {
  const int i = blockIdx.x * 256 + threadIdx.x;
  float4 v = src[i];
  float hx = __bfloat162float(__float2bfloat16(v.x));
  float hy = __bfloat162float(__float2bfloat16(v.y));
  float hz = __bfloat162float(__float2bfloat16(v.z));
  float hw = __bfloat162float(__float2bfloat16(v.w));
  ((uint2*)g_khi)[i] = make_uint2(pack2(hx, hy), pack2(hz, hw));
  ((uint2*)g_klo)[i] = make_uint2(pack2(v.x - hx, v.y - hy), pack2(v.z - hz, v.w - hw));
}

// ===========================================================================
// GEMM mainloop (shared shape, R8-frozen): tile 128x128, 256 thr, warp grid
// 4x2 (32x64 tiles), single 64KB buffer, register prefetch, PURE-COPY staging.
// ===========================================================================
#define GK      64
#define NCHUNK  (KDIM / GK)            // 12
#define OFF_AHI 0
#define OFF_ALO 16384
#define OFF_BHI 32768
#define OFF_BLO 49152
#define GEMM_SMEM 65536

#define GEMM_MAINLOOP(APH, APL, BPH, BPL)                                      \
  uint32_t dsw[4];                                                             \
  _Pragma("unroll")                                                            \
  for (int j = 0; j < 4; j++)                                                  \
    dsw[j] = SWZ((uint32_t)(r * 128 + cb * 2 + j * 16));                       \
  float acc[16][4];                                                            \
  _Pragma("unroll")                                                            \
  for (int i = 0; i < 16; i++)                                                 \
    _Pragma("unroll")                                                          \
    for (int j = 0; j < 4; j++) acc[i][j] = 0.f;                               \
  uint4 pah[4], pal[4], pwh[4], pwl[4];                                        \
  _Pragma("unroll")                                                            \
  for (int j = 0; j < 4; j++) {                                                \
    pah[j] = *(const uint4*)(APH + j * 8);                                     \
    pal[j] = *(const uint4*)(APL + j * 8);                                     \
    pwh[j] = *(const uint4*)(BPH + j * 8);                                     \
    pwl[j] = *(const uint4*)(BPL + j * 8);                                     \
  }                                                                            \
  for (int c = 0; c < NCHUNK; c++) {                                           \
    _Pragma("unroll")                                                          \
    for (int j = 0; j < 4; j++) {                                              \
      *(uint4*)(sm + OFF_AHI + dsw[j]) = pah[j];                               \
      *(uint4*)(sm + OFF_ALO + dsw[j]) = pal[j];                               \
      *(uint4*)(sm + OFF_BHI + dsw[j]) = pwh[j];                               \
      *(uint4*)(sm + OFF_BLO + dsw[j]) = pwl[j];                               \
    }                                                                          \
    __syncthreads();                                                           \
    if (c + 1 < NCHUNK) {                                                      \
      const int ko = (c + 1) * GK;                                             \
      _Pragma("unroll")                                                        \
      for (int j = 0; j < 4; j++) {                                            \
        pah[j] = *(const uint4*)(APH + ko + j * 8);                            \
        pal[j] = *(const uint4*)(APL + ko + j * 8);                            \
        pwh[j] = *(const uint4*)(BPH + ko + j * 8);                            \
        pwl[j] = *(const uint4*)(BPL + ko + j * 8);                            \
      }                                                                        \
    }                                                                          \
    _Pragma("unroll")                                                          \
    for (int ks = 0; ks < 4; ks++) {                                           \
      const uint32_t koff = (uint32_t)(ks * 32 + lkb);                         \
      uint32_t ah[2][4], al[2][4];                                             \
      _Pragma("unroll")                                                        \
      for (int mi = 0; mi < 2; mi++) {                                         \
        const uint32_t off = (uint32_t)((mw + mi * 16 + lrow) * 128) + koff;   \
        ldsm4(ah[mi], sbase + OFF_AHI + SWZ(off));                             \
        ldsm4(al[mi], sbase + OFF_ALO + SWZ(off));                             \
      }                                                                        \
      uint32_t bh[4][4], bl[4][4];                                             \
      _Pragma("unroll")                                                        \
      for (int nb = 0; nb < 4; nb++) {                                         \
        const uint32_t off = (uint32_t)((nw + nb * 16 + lrow) * 128) + koff;   \
        ldsm4(bh[nb], sbase + OFF_BHI + SWZ(off));                             \
        ldsm4(bl[nb], sbase + OFF_BLO + SWZ(off));                             \
      }                                                                        \
      _Pragma("unroll")                                                        \
      for (int ni = 0; ni < 8; ni++) {                                         \
        const int nb = ni >> 1, sel = ni & 1;                                  \
        const uint32_t bh0 = bh[nb][sel], bh1 = bh[nb][2 + sel];               \
        const uint32_t bl0 = bl[nb][sel], bl1 = bl[nb][2 + sel];               \
        _Pragma("unroll")                                                      \
        for (int mi = 0; mi < 2; mi++) {                                       \
          mma_bf16(acc[mi * 8 + ni], ah[mi], bh0, bh1);                        \
          mma_bf16(acc[mi * 8 + ni], ah[mi], bl0, bl1);                        \
          mma_bf16(acc[mi * 8 + ni], al[mi], bh0, bh1);                        \
        }                                                                      \
      }                                                                        \
    }                                                                          \
    __syncthreads();                                                           \
  }

// ---- QKV projection: A = x-splits (in d_out scratch), W = splits in g_chi.
// Epilogue: (acc+bias)*qs split to q/k/v hi/lo, (B,H,S,D) scatter.
__global__ __launch_bounds__(256) void gemm_qkv_kernel(
    const __nv_bfloat16* __restrict__ xsp,
    const float* __restrict__ b0, const float* __restrict__ b1,
    const float* __restrict__ b2) {
  extern __shared__ char sm[];
  const uint32_t sbase = smem_u32(sm);
  const int tid  = threadIdx.x;
  const int wid  = tid >> 5;
  const int lane = tid & 31;
  const int m0 = blockIdx.y * 128;
  const int n0 = blockIdx.x * 128;
  const int z  = blockIdx.z;

  const float* bias = (z == 0) ? b0 : (z == 1) ? b1 : b2;
  const int r  = tid >> 1;
  const int cb = (tid & 1) * 32;
  const __nv_bfloat16* Aph = xsp + (size_t)(m0 + r) * KDIM + cb;
  const __nv_bfloat16* Apl = Aph + (size_t)MTOT * KDIM;
  const __nv_bfloat16* Wph = g_chi + (size_t)z * WELEM + (size_t)(n0 + r) * KDIM + cb;
  const __nv_bfloat16* Wpl = g_clo + (size_t)z * WELEM + (size_t)(n0 + r) * KDIM + cb;

  const int mw = (wid >> 1) * 32;
  const int nw = (wid & 1) * 64;
  const int lrow = lane & 15;
  const int lkb  = (lane >> 4) * 16;

  GEMM_MAINLOOP(Aph, Apl, Wph, Wpl)

  __nv_bfloat16* ohi = (z == 0) ? g_qhi : (z == 1) ? g_khi : g_vhi;
  __nv_bfloat16* olo = (z == 0) ? g_qlo : (z == 1) ? g_klo : g_vlo;
  const float qs = (z == 0) ? 0.125f : 1.0f;
  const int er = lane >> 2;
  const int ec = (lane & 3) * 2;
#pragma unroll
  for (int mi = 0; mi < 2; mi++) {
#pragma unroll
    for (int rr = 0; rr < 2; rr++) {
      const int m = m0 + mw + mi * 16 + rr * 8 + er;
      const int b = m >> 11;
      const int s = m & 2047;
#pragma unroll
      for (int ni = 0; ni < 8; ni++) {
        const int n = n0 + nw + ni * 8 + ec;
        const int h = n >> 6;
        const int d = n & 63;
        float fx = (acc[mi * 8 + ni][rr * 2 + 0] + bias[n]) * qs;
        float fy = (acc[mi * 8 + ni][rr * 2 + 1] + bias[n + 1]) * qs;
        float hx = __bfloat162float(__float2bfloat16(fx));
        float hy = __bfloat162float(__float2bfloat16(fy));
        const size_t o = (((size_t)b * NUM_HEADS + h) * SEQ + s) * HEAD_DIM + d;
        *(uint32_t*)(ohi + o) = pack2(hx, hy);
        *(uint32_t*)(olo + o) = pack2(fx - hx, fy - hy);
      }
    }
  }
}

// ---- Output projection: A = ctx-splits (g_chi/g_clo), W = Wo-splits (g_khi).
__global__ __launch_bounds__(256) void gemm_out_kernel(
    const float* __restrict__ bias, float* __restrict__ dout) {
  extern __shared__ char sm[];
  const uint32_t sbase = smem_u32(sm);
  const int tid  = threadIdx.x;
  const int wid  = tid >> 5;
  const int lane = tid & 31;
  const int m0 = blockIdx.y * 128;
  const int n0 = blockIdx.x * 128;

  const int r  = tid >> 1;
  const int cb = (tid & 1) * 32;
  const __nv_bfloat16* Aph = g_chi + (size_t)(m0 + r) * KDIM + cb;
  const __nv_bfloat16* Apl = g_clo + (size_t)(m0 + r) * KDIM + cb;
  const __nv_bfloat16* Wph = g_khi + (size_t)(n0 + r) * KDIM + cb;
  const __nv_bfloat16* Wpl = g_klo + (size_t)(n0 + r) * KDIM + cb;

  const int mw = (wid >> 1) * 32;
  const int nw = (wid & 1) * 64;
  const int lrow = lane & 15;
  const int lkb  = (lane >> 4) * 16;

  GEMM_MAINLOOP(Aph, Apl, Wph, Wpl)

  const int er = lane >> 2;
  const int ec = (lane & 3) * 2;
#pragma unroll
  for (int mi = 0; mi < 2; mi++) {
#pragma unroll
    for (int rr = 0; rr < 2; rr++) {
      const int m = m0 + mw + mi * 16 + rr * 8 + er;
      float* orow = dout + (size_t)m * EMB;
#pragma unroll
      for (int ni = 0; ni < 8; ni++) {
        const int n = n0 + nw + ni * 8 + ec;
        float2 v;
        v.x = acc[mi * 8 + ni][rr * 2 + 0] + bias[n];
        v.y = acc[mi * 8 + ni][rr * 2 + 1] + bias[n + 1];
        *(float2*)(orow + n) = v;
      }
    }
  }
}

// ===========================================================================
// HMMA flash attention (R16-proven, unchanged): reads q/k/v splits (pure
// copies), writes ctx splits into g_chi/g_clo (W splits dead by then).
// ===========================================================================
#define AQ_HI   0
#define AQ_LO   8192
#define AB_HI   16384
#define AB_LO   32768
#define AP_HI   49152
#define AP_LO   65536
#define AREDM   81920
#define AREDS   82944
#define ATTN_SMEM 83968

__global__ __launch_bounds__(256, 2) void attn_kernel() {
  extern __shared__ char sm[];
  const uint32_t sbase = smem_u32(sm);
  float* REDM = (float*)(sm + AREDM);
  float* REDS = (float*)(sm + AREDS);

  const int tid  = threadIdx.x;
  const int wid  = tid >> 5;
  const int lane = tid & 31;
  int bx = blockIdx.x;
  const int qt  = bx & 3;   bx >>= 2;
  const int seg = bx & 7;   bx >>= 3;
  const int hh  = bx % NUM_HEADS;
  const int bb  = bx / NUM_HEADS;

  const size_t head_off = (((size_t)bb*NUM_HEADS + hh)*SEQ + seg*SEG) * HEAD_DIM;
  const size_t qoff = head_off + (size_t)qt*64*HEAD_DIM;

  const int mw   = (wid >> 2) * 32;
  const int wcol = wid & 3;
  const int lrow = lane & 15;
  const int lkb  = (lane >> 4) * 16;
  const int er   = lane >> 2;
  const int ec   = (lane & 3) * 2;
  const int nw2  = wcol * 16;
  const int trow = (lane & 7) + ((lane >> 4) << 3);
  const int tcol = ((lane >> 3) & 1) << 3;

  const int sr  = tid >> 1;
  const int scb = (tid & 1) * 32;

  {
    const int r   = tid >> 2;
    const int c0e = (tid & 3) * 16;
#pragma unroll
    for (int j = 0; j < 2; j++) {
      const uint32_t sw = SWZ((uint32_t)(r * 128 + c0e * 2 + j * 16));
      *(uint4*)(sm + AQ_HI + sw) = *(const uint4*)(g_qhi + qoff + r * 64 + c0e + j * 8);
      *(uint4*)(sm + AQ_LO + sw) = *(const uint4*)(g_qlo + qoff + r * 64 + c0e + j * 8);
    }
  }

  float accv[4][4];
#pragma unroll
  for (int i = 0; i < 4; i++)
#pragma unroll
    for (int j = 0; j < 4; j++) accv[i][j] = 0.f;
  float Mrow[2][2] = {{-1e30f, -1e30f}, {-1e30f, -1e30f}};
  float Lrow[2][2] = {{0.f, 0.f}, {0.f, 0.f}};

  for (int h = 0; h < 2; h++) {
    {
      const size_t so = head_off + (size_t)(h * 128 + sr) * 64 + scb;
#pragma unroll
      for (int j = 0; j < 4; j++) {
        const uint32_t sw = SWZ((uint32_t)(sr * 128 + scb * 2 + j * 16));
        *(uint4*)(sm + AB_HI + sw) = *(const uint4*)(g_khi + so + j * 8);
        *(uint4*)(sm + AB_LO + sw) = *(const uint4*)(g_klo + so + j * 8);
      }
    }
    __syncthreads();

    float sacc[8][4];
#pragma unroll
    for (int i = 0; i < 8; i++)
#pragma unroll
      for (int j = 0; j < 4; j++) sacc[i][j] = 0.f;

#pragma unroll
    for (int ks = 0; ks < 4; ks++) {
      const uint32_t koff = (uint32_t)(ks * 32 + lkb);
      uint32_t ah[2][4], al[2][4];
#pragma unroll
      for (int mi = 0; mi < 2; mi++) {
        const uint32_t off = (uint32_t)((mw + mi * 16 + lrow) * 128) + koff;
        ldsm4(ah[mi], sbase + AQ_HI + SWZ(off));
        ldsm4(al[mi], sbase + AQ_LO + SWZ(off));
      }
      uint32_t bh[2][4], bl[2][4];
#pragma unroll
      for (int nb = 0; nb < 2; nb++) {
        const uint32_t off = (uint32_t)((wcol * 32 + nb * 16 + lrow) * 128) + koff;
        ldsm4(bh[nb], sbase + AB_HI + SWZ(off));
        ldsm4(bl[nb], sbase + AB_LO + SWZ(off));
      }
#pragma unroll
      for (int ni = 0; ni < 4; ni++) {
        const int nb = ni >> 1, sel = ni & 1;
        const uint32_t b0 = bh[nb][sel], b1 = bh[nb][2 + sel];
        const uint32_t c0 = bl[nb][sel], c1 = bl[nb][2 + sel];
#pragma unroll
        for (int mi = 0; mi < 2; mi++) {
          mma_bf16(sacc[mi * 4 + ni], ah[mi], b0, b1);
          mma_bf16(sacc[mi * 4 + ni], ah[mi], c0, c1);
          mma_bf16(sacc[mi * 4 + ni], al[mi], b0, b1);
        }
      }
    }

#pragma unroll
    for (int mi = 0; mi < 2; mi++)
#pragma unroll
      for (int rr = 0; rr < 2; rr++) {
        float mx = -1e30f;
#pragma unroll
        for (int ni = 0; ni < 4; ni++) {
          mx = fmaxf(mx, sacc[mi * 4 + ni][rr * 2 + 0]);
          mx = fmaxf(mx, sacc[mi * 4 + ni][rr * 2 + 1]);
        }
        mx = fmaxf(mx, __shfl_xor_sync(0xffffffffu, mx, 1));
        mx = fmaxf(mx, __shfl_xor_sync(0xffffffffu, mx, 2));
        if ((lane & 3) == 0)
          REDM[wcol * 64 + mw + mi * 16 + rr * 8 + er] = mx;
      }
    __syncthreads();

    float fr[2][2];
#pragma unroll
    for (int mi = 0; mi < 2; mi++)
#pragma unroll
      for (int rr = 0; rr < 2; rr++) {
        const int m = mw + mi * 16 + rr * 8 + er;
        const float fm = fmaxf(fmaxf(REDM[m], REDM[64 + m]),
                               fmaxf(REDM[128 + m], REDM[192 + m]));
        const float Mn = fmaxf(Mrow[mi][rr], fm);
        fr[mi][rr] = __expf(Mrow[mi][rr] - Mn);
        Mrow[mi][rr] = Mn;
        float s = 0.f;
#pragma unroll
        for (int ni = 0; ni < 4; ni++) {
          float e0 = __expf(sacc[mi * 4 + ni][rr * 2 + 0] - Mn);
          float e1 = __expf(sacc[mi * 4 + ni][rr * 2 + 1] - Mn);
          s += e0 + e1;
          const int colh = wcol * 32 + ni * 8 + ec;
          const int p = colh >> 6, cp = colh & 63;
          float h0 = __bfloat162float(__float2bfloat16(e0));
          float h1 = __bfloat162float(__float2bfloat16(e1));
          const uint32_t sw = SWZ((uint32_t)(m * 128 + cp * 2));
          *(uint32_t*)(sm + AP_HI + p * 8192 + sw) = pack2(h0, h1);
          *(uint32_t*)(sm + AP_LO + p * 8192 + sw) = pack2(e0 - h0, e1 - h1);
        }
        s += __shfl_xor_sync(0xffffffffu, s, 1);
        s += __shfl_xor_sync(0xffffffffu, s, 2);
        if ((lane & 3) == 0) REDS[wcol * 64 + m] = s;
      }
    {
      const size_t so = head_off + (size_t)(h * 128 + sr) * 64 + scb;
#pragma unroll
      for (int j = 0; j < 4; j++) {
        const uint32_t sw = SWZ((uint32_t)(sr * 128 + scb * 2 + j * 16));
        *(uint4*)(sm + AB_HI + sw) = *(const uint4*)(g_vhi + so + j * 8);
        *(uint4*)(sm + AB_LO + sw) = *(const uint4*)(g_vlo + so + j * 8);
      }
    }
    __syncthreads();

#pragma unroll
    for (int mi = 0; mi < 2; mi++)
#pragma unroll
      for (int rr = 0; rr < 2; rr++) {
        const int m = mw + mi * 16 + rr * 8 + er;
        const float sh = REDS[m] + REDS[64 + m] + REDS[128 + m] + REDS[192 + m];
        const float f = fr[mi][rr];
        Lrow[mi][rr] = Lrow[mi][rr] * f + sh;
#pragma unroll
        for (int ni = 0; ni < 2; ni++) {
          accv[mi * 2 + ni][rr * 2 + 0] *= f;
          accv[mi * 2 + ni][rr * 2 + 1] *= f;
        }
      }

#pragma unroll
    for (int pp = 0; pp < 2; pp++) {
      const uint32_t pb = (uint32_t)pp * 8192;
#pragma unroll
      for (int ks = 0; ks < 4; ks++) {
        const uint32_t koff = (uint32_t)(ks * 32 + lkb);
        uint32_t ph[2][4], pl[2][4];
#pragma unroll
        for (int mi = 0; mi < 2; mi++) {
          const uint32_t off = (uint32_t)((mw + mi * 16 + lrow) * 128) + koff;
          ldsm4(ph[mi], sbase + AP_HI + pb + SWZ(off));
          ldsm4(pl[mi], sbase + AP_LO + pb + SWZ(off));
        }
        uint32_t vh[4], vl[4];
        {
          const int jg = pp * 64 + ks * 16 + trow;
          const uint32_t off = SWZ((uint32_t)(jg * 128 + (nw2 + tcol) * 2));
          ldsm4t(vh, sbase + AB_HI + off);
          ldsm4t(vl, sbase + AB_LO + off);
        }
#pragma unroll
        for (int ni = 0; ni < 2; ni++) {
          const uint32_t b0 = vh[ni], b1 = vh[2 + ni];
          const uint32_t c0 = vl[ni], c1 = vl[2 + ni];
#pragma unroll
          for (int mi = 0; mi < 2; mi++) {
            mma_bf16(accv[mi * 2 + ni], ph[mi], b0, b1);
            mma_bf16(accv[mi * 2 + ni], ph[mi], c0, c1);
            mma_bf16(accv[mi * 2 + ni], pl[mi], b0, b1);
          }
        }
      }
    }
    __syncthreads();
  }

  const size_t cb0 = ((size_t)bb*SEQ + seg*SEG + qt*64)*EMB + hh*64;
#pragma unroll
  for (int mi = 0; mi < 2; mi++) {
#pragma unroll
    for (int rr = 0; rr < 2; rr++) {
      const int m = mw + mi * 16 + rr * 8 + er;
      const float iv = 1.0f / Lrow[mi][rr];
#pragma unroll
      for (int ni = 0; ni < 2; ni++) {
        const int d = nw2 + ni * 8 + ec;
        float fx = accv[mi * 2 + ni][rr * 2 + 0] * iv;
        float fy = accv[mi * 2 + ni][rr * 2 + 1] * iv;
        float hx = __bfloat162float(__float2bfloat16(fx));
        float hy = __bfloat162float(__float2bfloat16(fy));
        const size_t o = cb0 + (size_t)m * EMB + d;
        *(uint32_t*)(g_chi + o) = pack2(hx, hy);
        *(uint32_t*)(g_clo + o) = pack2(fx - hx, fy - hy);
      }
    }
  }
}

// ===========================================================================
extern "C" void kernel_launch(void* const* d_in, const int* in_sizes, int n_in,
                              void* d_out, int out_size) {
  const float* x  = (const float*)d_in[0];
  const float* Wq = (const float*)d_in[1];
  const float* bq = (const float*)d_in[2];
  const float* Wk = (const float*)d_in[3];
  const float* bk = (const float*)d_in[4];
  const float* Wv = (const float*)d_in[5];
  const float* bv = (const float*)d_in[6];
  const float* Wo = (const float*)d_in[7];
  const float* bo = (const float*)d_in[8];
  float* out = (float*)d_out;
  __nv_bfloat16* xsp = (__nv_bfloat16*)d_out;   // d_out doubles as x-split scratch

  cudaFuncSetAttribute(gemm_qkv_kernel,
                       cudaFuncAttributeMaxDynamicSharedMemorySize, GEMM_SMEM);
  cudaFuncSetAttribute(gemm_out_kernel,
                       cudaFuncAttributeMaxDynamicSharedMemorySize, GEMM_SMEM);
  cudaFuncSetAttribute(attn_kernel,
                       cudaFuncAttributeMaxDynamicSharedMemorySize, ATTN_SMEM);

  // pre-splits: x -> d_out halves, Wq/Wk/Wv -> g_chi/g_clo
  convx_kernel<<<MTOT * KDIM / 4 / 256, 256>>>((const float4*)x, xsp);
  convw3_kernel<<<dim3(WELEM / 4 / 256, 3), 256>>>((const float4*)Wq,
                                                   (const float4*)Wk,
                                                   (const float4*)Wv);

  dim3 gqkv(6, 32, 3);
  gemm_qkv_kernel<<<gqkv, 256, GEMM_SMEM>>>(xsp, bq, bk, bv);

  attn_kernel<<<768, 256, ATTN_SMEM>>>();   // ctx-splits overwrite W-splits

  convwo_kernel<<<WELEM / 4 / 256, 256>>>((const float4*)Wo);  // into g_khi/g_klo

  dim3 gout(6, 32);
  gemm_out_kernel<<<gout, 256, GEMM_SMEM>>>(bo, out);
}